// round 12
// baseline (speedup 1.0000x reference)
#include <cuda_runtime.h>
#include <cuda_fp16.h>

#define ND 32
#define MAXN 100000
#define MAXE 1600000

static constexpr size_t SLOT = (size_t)MAXN * ND;

// Scratch arena (floats):
//  h1,h2 : 2 * SLOT fp32
//  T0h,T1h,X1h,fsh,fdh : 5 * SLOT/2 (fp16 rows)
//  csr_src : MAXE int
//  tail: deg(N), rs(N+1), cursor(N), blk(128)
__device__ __align__(256) float g_buf[5 * SLOT + (size_t)MAXE + 6 * (size_t)MAXN + 2048];

__device__ __forceinline__ float leaky(float x, float s) {
    return x > 0.0f ? x : s * x;
}
__device__ __forceinline__ uint2 f4_to_h4(float4 v) {
    __half2 a = __floats2half2_rn(v.x, v.y);
    __half2 b = __floats2half2_rn(v.z, v.w);
    uint2 r;
    r.x = *(unsigned*)&a;
    r.y = *(unsigned*)&b;
    return r;
}
__device__ __forceinline__ float4 h4_to_f4(uint2 u) {
    __half2 a = *(__half2*)&u.x;
    __half2 b = *(__half2*)&u.y;
    float2 fa = __half22float2(a), fb = __half22float2(b);
    return make_float4(fa.x, fa.y, fb.x, fb.y);
}
// unpack uint4 (8 halves) into 8 floats
__device__ __forceinline__ void u4_to_f8(uint4 u, float* f) {
    float4 a = h4_to_f4(make_uint2(u.x, u.y));
    float4 b = h4_to_f4(make_uint2(u.z, u.w));
    f[0] = a.x; f[1] = a.y; f[2] = a.z; f[3] = a.w;
    f[4] = b.x; f[5] = b.y; f[6] = b.z; f[7] = b.w;
}

// ---------------------------------------------------------------------------
// degree + scan + CSR fill  (deg zeroed by k_gat at end of previous run;
// static zero-init covers the first call)
// ---------------------------------------------------------------------------
__global__ void k_deg(const int* __restrict__ dst, int* __restrict__ deg, int E) {
    int e = blockIdx.x * blockDim.x + threadIdx.x;
    if (e < E) atomicAdd(&deg[dst[e]], 1);
}

__global__ void k_scan1(const int* __restrict__ deg, int* __restrict__ rs,
                        int* __restrict__ blk, int n) {
    __shared__ int sh[1024];
    int i = blockIdx.x * 1024 + threadIdx.x;
    int v = (i < n) ? deg[i] : 0;
    sh[threadIdx.x] = v;
    __syncthreads();
#pragma unroll
    for (int o = 1; o < 1024; o <<= 1) {
        int t = (threadIdx.x >= o) ? sh[threadIdx.x - o] : 0;
        __syncthreads();
        sh[threadIdx.x] += t;
        __syncthreads();
    }
    if (i < n) rs[i] = sh[threadIdx.x] - v;
    if (threadIdx.x == 1023) blk[blockIdx.x] = sh[1023];
}

__global__ void k_scan2(int* __restrict__ blk, int nb) {
    __shared__ int sh[128];
    int t = threadIdx.x;
    int v = (t < nb) ? blk[t] : 0;
    sh[t] = v;
    __syncthreads();
#pragma unroll
    for (int o = 1; o < 128; o <<= 1) {
        int x = (t >= o) ? sh[t - o] : 0;
        __syncthreads();
        sh[t] += x;
        __syncthreads();
    }
    if (t < nb) blk[t] = sh[t] - v;
}

// finalize row starts + cursors; also T0h = half(emb * dinv)  (fused prescale)
__global__ void k_scan3p(int* __restrict__ rs, int* __restrict__ cursor,
                         const int* __restrict__ blk, const int* __restrict__ deg,
                         const float4* __restrict__ emb, uint2* __restrict__ T0h,
                         int n, int E) {
    int i = blockIdx.x * blockDim.x + threadIdx.x;
    if (i >= n * 8) return;
    int node = i >> 3;
    float dv = rsqrtf(fmaxf((float)__ldg(deg + node), 1.0f));
    float4 v = __ldg(emb + i);
    v.x *= dv; v.y *= dv; v.z *= dv; v.w *= dv;
    T0h[i] = f4_to_h4(v);
    if ((i & 7) == 0) {
        int p = rs[node] + blk[node >> 10];
        rs[node] = p;
        cursor[node] = p;
        if (node == 0) rs[n] = E;
    }
}

__global__ void k_fill(const int* __restrict__ src, const int* __restrict__ dst,
                       int* __restrict__ cursor, int* __restrict__ csr_src, int E) {
    int e = blockIdx.x * blockDim.x + threadIdx.x;
    if (e >= E) return;
    int p = atomicAdd(&cursor[dst[e]], 1);
    csr_src[p] = src[e];
}

// ---------------------------------------------------------------------------
// warp-per-node CSR row sum over fp16 rows: 8 edges x 4 lanes (uint4/lane),
// fp32 accum. g = lane>>2 in 0..7, c = lane&3. Lane accumulates elements
// [c*8, c*8+8). After cross-group reduce, all lanes with same c hold the sum.
// ---------------------------------------------------------------------------
__device__ __forceinline__ void row_sum8(int beg, int end,
                                         const int* __restrict__ csr_src,
                                         const uint4* __restrict__ Th,
                                         int g, int c, float* acc) {
#pragma unroll
    for (int k = 0; k < 8; k++) acc[k] = 0.0f;
    float tmp[8];
    int base = beg;
    for (; base + 16 <= end; base += 16) {
        int i0 = __ldg(csr_src + base + g);
        int i1 = __ldg(csr_src + base + 8 + g);
        uint4 u0 = __ldg(Th + (size_t)i0 * 4 + c);
        uint4 u1 = __ldg(Th + (size_t)i1 * 4 + c);
        u4_to_f8(u0, tmp);
#pragma unroll
        for (int k = 0; k < 8; k++) acc[k] += tmp[k];
        u4_to_f8(u1, tmp);
#pragma unroll
        for (int k = 0; k < 8; k++) acc[k] += tmp[k];
    }
    for (; base < end; base += 8) {
        int p = base + g;
        if (p < end) {
            int i0 = __ldg(csr_src + p);
            uint4 u0 = __ldg(Th + (size_t)i0 * 4 + c);
            u4_to_f8(u0, tmp);
#pragma unroll
            for (int k = 0; k < 8; k++) acc[k] += tmp[k];
        }
    }
#pragma unroll
    for (int o = 4; o <= 16; o <<= 1) {
#pragma unroll
        for (int k = 0; k < 8; k++)
            acc[k] += __shfl_xor_sync(0xffffffffu, acc[k], o);
    }
}

// X1h = half(-r*acc*dv + (r-1)*f); T1h = half(X1*dv)
__global__ void k_chebA(const int* __restrict__ rs, const int* __restrict__ csr_src,
                        const uint4* __restrict__ Tin, const float4* __restrict__ f,
                        const int* __restrict__ deg, const float* __restrict__ lam,
                        uint2* __restrict__ X1h, uint2* __restrict__ Tout, int n) {
    int v = blockIdx.x * 8 + threadIdx.y;
    if (v >= n) return;
    int lane = threadIdx.x;
    int g = lane >> 2, c = lane & 3;
    int beg = rs[v], end = rs[v + 1];
    float acc[8];
    row_sum8(beg, end, csr_src, Tin, g, c, acc);
    if (g == 0) {
        float r = 2.0f / lam[0];
        float dv = rsqrtf(fmaxf((float)__ldg(deg + v), 1.0f));
        float4 fa = __ldg(f + (size_t)v * 8 + 2 * c);
        float4 fb = __ldg(f + (size_t)v * 8 + 2 * c + 1);
        float fv[8] = {fa.x, fa.y, fa.z, fa.w, fb.x, fb.y, fb.z, fb.w};
        float x1[8], t1[8];
#pragma unroll
        for (int k = 0; k < 8; k++) {
            x1[k] = -r * acc[k] * dv + (r - 1.0f) * fv[k];
            t1[k] = x1[k] * dv;
        }
        X1h[(size_t)v * 8 + 2 * c]     = f4_to_h4(make_float4(x1[0], x1[1], x1[2], x1[3]));
        X1h[(size_t)v * 8 + 2 * c + 1] = f4_to_h4(make_float4(x1[4], x1[5], x1[6], x1[7]));
        Tout[(size_t)v * 8 + 2 * c]     = f4_to_h4(make_float4(t1[0], t1[1], t1[2], t1[3]));
        Tout[(size_t)v * 8 + 2 * c + 1] = f4_to_h4(make_float4(t1[4], t1[5], t1[6], t1[7]));
    }
}

// Fused: acc = L-gather(T1h); X2 = -2r*acc*dv + 2(r-1)*X1 - f;
// out = leaky([X0,X1,X2] @ W + b); optional Tout_h = half(out*dinv)
__global__ void k_chebBL(const int* __restrict__ rs, const int* __restrict__ csr_src,
                         const uint4* __restrict__ Tin, const uint2* __restrict__ X1h,
                         const float4* __restrict__ f, const int* __restrict__ deg,
                         const float* __restrict__ lam, const float* __restrict__ W,
                         const float* __restrict__ b, float* __restrict__ out,
                         __half* __restrict__ Tout, int n) {
    __shared__ float sW[96 * 32];
    __shared__ float sb[32];
    __shared__ float sX[8][96];
    int t = threadIdx.y * 32 + threadIdx.x;
    for (int i = t; i < 96 * 32; i += 256) sW[i] = W[i];
    if (t < 32) sb[t] = b[t];
    __syncthreads();

    int v = blockIdx.x * 8 + threadIdx.y;
    if (v >= n) return;
    int lane = threadIdx.x;
    int g = lane >> 2, c = lane & 3;
    int beg = rs[v], end = rs[v + 1];
    float acc[8];
    row_sum8(beg, end, csr_src, Tin, g, c, acc);
    float dv = rsqrtf(fmaxf((float)__ldg(deg + v), 1.0f));
    if (g == 0) {
        float r = 2.0f / lam[0];
        float4 xa = h4_to_f4(__ldg(X1h + (size_t)v * 8 + 2 * c));
        float4 xb = h4_to_f4(__ldg(X1h + (size_t)v * 8 + 2 * c + 1));
        float x1[8] = {xa.x, xa.y, xa.z, xa.w, xb.x, xb.y, xb.z, xb.w};
        float4 fa = __ldg(f + (size_t)v * 8 + 2 * c);
        float4 fb = __ldg(f + (size_t)v * 8 + 2 * c + 1);
        float fv[8] = {fa.x, fa.y, fa.z, fa.w, fb.x, fb.y, fb.z, fb.w};
        float* sx = sX[threadIdx.y];
#pragma unroll
        for (int k = 0; k < 8; k++) {
            float x2 = -2.0f * r * acc[k] * dv + 2.0f * (r - 1.0f) * x1[k] - fv[k];
            sx[c * 8 + k] = fv[k];
            sx[32 + c * 8 + k] = x1[k];
            sx[64 + c * 8 + k] = x2;
        }
    }
    __syncwarp();
    const float* sx = sX[threadIdx.y];
    float s = sb[lane];
#pragma unroll
    for (int j = 0; j < 96; j++) s += sx[j] * sW[j * 32 + lane];
    s = leaky(s, 0.01f);
    out[(size_t)v * ND + lane] = s;
    if (Tout) Tout[(size_t)v * ND + lane] = __float2half(s * dv);
}

// fs_h = half(h@Ws+bs) ; fd_h = half(h@Wd+bd)
__global__ void k_fsfd(const float* __restrict__ h, const float* __restrict__ Ws,
                       const float* __restrict__ bs, const float* __restrict__ Wd,
                       const float* __restrict__ bd, __half* __restrict__ fsh,
                       __half* __restrict__ fdh, int n) {
    __shared__ float sWs[32 * 32], sWd[32 * 32], sbs[32], sbd[32];
    int t = threadIdx.y * 32 + threadIdx.x;
    for (int i = t; i < 1024; i += 256) { sWs[i] = Ws[i]; sWd[i] = Wd[i]; }
    if (t < 32) { sbs[t] = bs[t]; sbd[t] = bd[t]; }
    __syncthreads();
    int node = blockIdx.x * 8 + threadIdx.y;
    if (node >= n) return;
    int col = threadIdx.x;
    float a = sbs[col], c = sbd[col];
    const float* hr = h + (size_t)node * ND;
#pragma unroll
    for (int j = 0; j < 32; j++) {
        float x = hr[j];
        a += x * sWs[j * 32 + col];
        c += x * sWd[j * 32 + col];
    }
    fsh[(size_t)node * ND + col] = __float2half(a);
    fdh[(size_t)node * ND + col] = __float2half(c);
}

// ---------------------------------------------------------------------------
// fused GATv2: one CSR pass, plain softmax, 8 edges x 4 lanes per warp,
// fs/fd rows fp16 (uint4 = 8 features per lane). Re-zeros deg for next run.
// ---------------------------------------------------------------------------
__global__ void k_gat(const int* __restrict__ rs, const int* __restrict__ csr_src,
                      const uint4* __restrict__ fsh, const uint4* __restrict__ fdh,
                      const float* __restrict__ attn, float4* __restrict__ out,
                      int* __restrict__ deg, int n) {
    int v = blockIdx.x * 8 + threadIdx.y;
    if (v >= n) return;
    int lane = threadIdx.x;
    int g = lane >> 2, c = lane & 3;
    int beg = rs[v], end = rs[v + 1];
    float fdv[8], w[8];
    u4_to_f8(__ldg(fdh + (size_t)v * 4 + c), fdv);
#pragma unroll
    for (int k = 0; k < 8; k++) w[k] = __ldg(attn + c * 8 + k);
    float den = 0.0f;
    float acc[8];
#pragma unroll
    for (int k = 0; k < 8; k++) acc[k] = 0.0f;
    float f0[8], f1[8];
    int base = beg;
    for (; base + 16 <= end; base += 16) {
        int s0 = __ldg(csr_src + base + g);
        int s1 = __ldg(csr_src + base + 8 + g);
        uint4 u0 = __ldg(fsh + (size_t)s0 * 4 + c);
        uint4 u1 = __ldg(fsh + (size_t)s1 * 4 + c);
        u4_to_f8(u0, f0);
        u4_to_f8(u1, f1);
        float t0 = 0.0f, t1 = 0.0f;
#pragma unroll
        for (int k = 0; k < 8; k++) {
            t0 += leaky(f0[k] + fdv[k], 0.2f) * w[k];
            t1 += leaky(f1[k] + fdv[k], 0.2f) * w[k];
        }
        t0 += __shfl_xor_sync(0xffffffffu, t0, 1);
        t0 += __shfl_xor_sync(0xffffffffu, t0, 2);
        t1 += __shfl_xor_sync(0xffffffffu, t1, 1);
        t1 += __shfl_xor_sync(0xffffffffu, t1, 2);
        float e0 = __expf(t0);
        float e1 = __expf(t1);
        den += e0 + e1;
#pragma unroll
        for (int k = 0; k < 8; k++) acc[k] += f0[k] * e0 + f1[k] * e1;
    }
    for (; base < end; base += 8) {
        int p = base + g;
        bool valid = p < end;
        int s0 = valid ? __ldg(csr_src + p) : 0;
        uint4 u0 = __ldg(fsh + (size_t)s0 * 4 + c);
        u4_to_f8(u0, f0);
        float t0 = 0.0f;
#pragma unroll
        for (int k = 0; k < 8; k++) t0 += leaky(f0[k] + fdv[k], 0.2f) * w[k];
        t0 += __shfl_xor_sync(0xffffffffu, t0, 1);  // all lanes participate
        t0 += __shfl_xor_sync(0xffffffffu, t0, 2);
        if (valid) {
            float e0 = __expf(t0);
            den += e0;
#pragma unroll
            for (int k = 0; k < 8; k++) acc[k] += f0[k] * e0;
        }
    }
#pragma unroll
    for (int o = 4; o <= 16; o <<= 1) {
        den += __shfl_xor_sync(0xffffffffu, den, o);
#pragma unroll
        for (int k = 0; k < 8; k++)
            acc[k] += __shfl_xor_sync(0xffffffffu, acc[k], o);
    }
    if (g == 0) {
        float inv = (den > 0.0f) ? 1.0f / den : 0.0f;
        float4 o0, o1;
        o0.x = leaky(acc[0] * inv, 0.01f);
        o0.y = leaky(acc[1] * inv, 0.01f);
        o0.z = leaky(acc[2] * inv, 0.01f);
        o0.w = leaky(acc[3] * inv, 0.01f);
        o1.x = leaky(acc[4] * inv, 0.01f);
        o1.y = leaky(acc[5] * inv, 0.01f);
        o1.z = leaky(acc[6] * inv, 0.01f);
        o1.w = leaky(acc[7] * inv, 0.01f);
        out[(size_t)v * 8 + 2 * c] = o0;
        out[(size_t)v * 8 + 2 * c + 1] = o1;
        if (c == 0) deg[v] = 0;  // ready for next run / replay
    }
}

// ---------------------------------------------------------------------------
// launch
// ---------------------------------------------------------------------------
extern "C" void kernel_launch(void* const* d_in, const int* in_sizes, int n_in,
                              void* d_out, int out_size) {
    const int*   src  = (const int*)d_in[0];
    const int*   dst  = (const int*)d_in[1];
    const float* emb  = (const float*)d_in[2];
    const float* lam  = (const float*)d_in[3];
    const float* chW  = (const float*)d_in[4];
    const float* chb  = (const float*)d_in[5];
    const float* Ws   = (const float*)d_in[6];
    const float* bs   = (const float*)d_in[7];
    const float* Wd   = (const float*)d_in[8];
    const float* bd   = (const float*)d_in[9];
    const float* attn = (const float*)d_in[10];

    const int E = in_sizes[0];
    const int n = in_sizes[2] / ND;

    float* base = nullptr;
    cudaGetSymbolAddress((void**)&base, g_buf);

    float*  h1      = base;
    float*  h2      = base + 1 * SLOT;
    __half* T0h     = (__half*)(base + 2 * SLOT);
    __half* T1h     = (__half*)(base + 2 * SLOT + SLOT / 2);
    __half* X1h     = (__half*)(base + 3 * SLOT);
    __half* fsh     = (__half*)(base + 3 * SLOT + SLOT / 2);
    __half* fdh     = (__half*)(base + 4 * SLOT);
    int*    csr_src = (int*)(base + 5 * SLOT);
    float*  tail    = base + 5 * SLOT + MAXE;
    int*    deg     = (int*)tail;
    int*    rs      = (int*)(tail + MAXN);          // N+1
    int*    cursor  = (int*)(tail + 2 * MAXN + 64);
    int*    blk     = (int*)(tail + 3 * MAXN + 64);

    const int nt = 256;
    auto g = [&](long x) { return (int)((x + nt - 1) / nt); };
    const int gV4   = g((long)n * 8);
    const int gEdge = g((long)E);
    const int gNW   = (n + 7) / 8;
    dim3 bNW(32, 8);
    const int nb = (n + 1023) / 1024;

    // --- CSR build (deg already zero: static init / re-zeroed by k_gat) ---
    k_deg<<<gEdge, nt>>>(dst, deg, E);
    k_scan1<<<nb, 1024>>>(deg, rs, blk, n);
    k_scan2<<<1, 128>>>(blk, nb);
    k_scan3p<<<gV4, nt>>>(rs, cursor, blk, deg, (const float4*)emb, (uint2*)T0h, n, E);
    k_fill<<<gEdge, nt>>>(src, dst, cursor, csr_src, E);

    // --- ChebConv 1 (input = embedding) ---
    k_chebA<<<gNW, bNW>>>(rs, csr_src, (const uint4*)T0h, (const float4*)emb,
                          deg, lam, (uint2*)X1h, (uint2*)T1h, n);
    k_chebBL<<<gNW, bNW>>>(rs, csr_src, (const uint4*)T1h, (const uint2*)X1h,
                           (const float4*)emb, deg, lam, chW, chb, h1, T0h, n);

    // --- ChebConv 2 (input = h1; T0h = h1*dinv) ---
    k_chebA<<<gNW, bNW>>>(rs, csr_src, (const uint4*)T0h, (const float4*)h1,
                          deg, lam, (uint2*)X1h, (uint2*)T1h, n);
    k_chebBL<<<gNW, bNW>>>(rs, csr_src, (const uint4*)T1h, (const uint2*)X1h,
                           (const float4*)h1, deg, lam, chW, chb, h2, nullptr, n);

    // --- GATv2 (fused single pass, fp16 fs/fd, plain softmax) ---
    k_fsfd<<<gNW, bNW>>>(h2, Ws, bs, Wd, bd, fsh, fdh, n);
    k_gat<<<gNW, bNW>>>(rs, csr_src, (const uint4*)fsh, (const uint4*)fdh,
                        attn, (float4*)d_out, deg, n);
}

// round 13
// speedup vs baseline: 1.1291x; 1.1291x over previous
#include <cuda_runtime.h>
#include <cuda_fp16.h>

#define ND 32
#define MAXN 100000
#define MAXE 1600000

static constexpr size_t SLOT = (size_t)MAXN * ND;

// Scratch arena (floats):
//  h1,h2 : 2 * SLOT fp32
//  T0h,T1h,X1h,fsh,fdh : 5 * SLOT/2 (fp16 rows)
//  csr_src : MAXE int
//  tail: deg(N), rs(N+1), cursor(N), blk(128)
__device__ __align__(256) float g_buf[5 * SLOT + (size_t)MAXE + 6 * (size_t)MAXN + 2048];

__device__ __forceinline__ float leaky(float x, float s) {
    return x > 0.0f ? x : s * x;
}
__device__ __forceinline__ uint2 f4_to_h4(float4 v) {
    __half2 a = __floats2half2_rn(v.x, v.y);
    __half2 b = __floats2half2_rn(v.z, v.w);
    uint2 r;
    r.x = *(unsigned*)&a;
    r.y = *(unsigned*)&b;
    return r;
}
__device__ __forceinline__ float4 h4_to_f4(uint2 u) {
    __half2 a = *(__half2*)&u.x;
    __half2 b = *(__half2*)&u.y;
    float2 fa = __half22float2(a), fb = __half22float2(b);
    return make_float4(fa.x, fa.y, fb.x, fb.y);
}

// ---------------------------------------------------------------------------
// degree + scan + CSR fill  (deg zeroed by k_gat at end of previous run;
// static zero-init covers the first call)
// ---------------------------------------------------------------------------
__global__ void k_deg(const int* __restrict__ dst, int* __restrict__ deg, int E) {
    int e = blockIdx.x * blockDim.x + threadIdx.x;
    if (e < E) atomicAdd(&deg[dst[e]], 1);
}

__global__ void k_scan1(const int* __restrict__ deg, int* __restrict__ rs,
                        int* __restrict__ blk, int n) {
    __shared__ int sh[1024];
    int i = blockIdx.x * 1024 + threadIdx.x;
    int v = (i < n) ? deg[i] : 0;
    sh[threadIdx.x] = v;
    __syncthreads();
#pragma unroll
    for (int o = 1; o < 1024; o <<= 1) {
        int t = (threadIdx.x >= o) ? sh[threadIdx.x - o] : 0;
        __syncthreads();
        sh[threadIdx.x] += t;
        __syncthreads();
    }
    if (i < n) rs[i] = sh[threadIdx.x] - v;
    if (threadIdx.x == 1023) blk[blockIdx.x] = sh[1023];
}

__global__ void k_scan2(int* __restrict__ blk, int nb) {
    __shared__ int sh[128];
    int t = threadIdx.x;
    int v = (t < nb) ? blk[t] : 0;
    sh[t] = v;
    __syncthreads();
#pragma unroll
    for (int o = 1; o < 128; o <<= 1) {
        int x = (t >= o) ? sh[t - o] : 0;
        __syncthreads();
        sh[t] += x;
        __syncthreads();
    }
    if (t < nb) blk[t] = sh[t] - v;
}

// finalize row starts + cursors; also T0h = half(emb * dinv)  (fused prescale)
__global__ void k_scan3p(int* __restrict__ rs, int* __restrict__ cursor,
                         const int* __restrict__ blk, const int* __restrict__ deg,
                         const float4* __restrict__ emb, uint2* __restrict__ T0h,
                         int n, int E) {
    int i = blockIdx.x * blockDim.x + threadIdx.x;
    if (i >= n * 8) return;
    int node = i >> 3;
    float dv = rsqrtf(fmaxf((float)__ldg(deg + node), 1.0f));
    float4 v = __ldg(emb + i);
    v.x *= dv; v.y *= dv; v.z *= dv; v.w *= dv;
    T0h[i] = f4_to_h4(v);
    if ((i & 7) == 0) {
        int p = rs[node] + blk[node >> 10];
        rs[node] = p;
        cursor[node] = p;
        if (node == 0) rs[n] = E;
    }
}

__global__ void k_fill(const int* __restrict__ src, const int* __restrict__ dst,
                       int* __restrict__ cursor, int* __restrict__ csr_src, int E) {
    int e = blockIdx.x * blockDim.x + threadIdx.x;
    if (e >= E) return;
    int p = atomicAdd(&cursor[dst[e]], 1);
    csr_src[p] = src[e];
}

// ---------------------------------------------------------------------------
// warp-per-node CSR row sum over fp16 rows: 4 edges x 8 lanes (uint2/lane),
// up to 4 rows in flight per group. fp32 accum.
// ---------------------------------------------------------------------------
__device__ __forceinline__ float4 row_sum4h(int beg, int end,
                                            const int* __restrict__ csr_src,
                                            const uint2* __restrict__ Th,
                                            int g, int c) {
    float4 acc = make_float4(0.f, 0.f, 0.f, 0.f);
    int base = beg;
    for (; base + 16 <= end; base += 16) {
        int i0 = __ldg(csr_src + base + g);
        int i1 = __ldg(csr_src + base + 4 + g);
        int i2 = __ldg(csr_src + base + 8 + g);
        int i3 = __ldg(csr_src + base + 12 + g);
        float4 v0 = h4_to_f4(__ldg(Th + (size_t)i0 * 8 + c));
        float4 v1 = h4_to_f4(__ldg(Th + (size_t)i1 * 8 + c));
        float4 v2 = h4_to_f4(__ldg(Th + (size_t)i2 * 8 + c));
        float4 v3 = h4_to_f4(__ldg(Th + (size_t)i3 * 8 + c));
        acc.x += (v0.x + v1.x) + (v2.x + v3.x);
        acc.y += (v0.y + v1.y) + (v2.y + v3.y);
        acc.z += (v0.z + v1.z) + (v2.z + v3.z);
        acc.w += (v0.w + v1.w) + (v2.w + v3.w);
    }
    for (; base + 8 <= end; base += 8) {
        int i0 = __ldg(csr_src + base + g);
        int i1 = __ldg(csr_src + base + 4 + g);
        float4 v0 = h4_to_f4(__ldg(Th + (size_t)i0 * 8 + c));
        float4 v1 = h4_to_f4(__ldg(Th + (size_t)i1 * 8 + c));
        acc.x += v0.x + v1.x;
        acc.y += v0.y + v1.y;
        acc.z += v0.z + v1.z;
        acc.w += v0.w + v1.w;
    }
    for (; base < end; base += 4) {
        int p = base + g;
        if (p < end) {
            int i0 = __ldg(csr_src + p);
            float4 v0 = h4_to_f4(__ldg(Th + (size_t)i0 * 8 + c));
            acc.x += v0.x; acc.y += v0.y; acc.z += v0.z; acc.w += v0.w;
        }
    }
#pragma unroll
    for (int o = 8; o <= 16; o <<= 1) {
        acc.x += __shfl_xor_sync(0xffffffffu, acc.x, o);
        acc.y += __shfl_xor_sync(0xffffffffu, acc.y, o);
        acc.z += __shfl_xor_sync(0xffffffffu, acc.z, o);
        acc.w += __shfl_xor_sync(0xffffffffu, acc.w, o);
    }
    return acc;
}

// X1h = half(-r*acc*dv + (r-1)*f); T1h = half(X1*dv)
__global__ void k_chebA(const int* __restrict__ rs, const int* __restrict__ csr_src,
                        const uint2* __restrict__ Tin, const float4* __restrict__ f,
                        const int* __restrict__ deg, const float* __restrict__ lam,
                        uint2* __restrict__ X1h, uint2* __restrict__ Tout, int n) {
    int v = blockIdx.x * 8 + threadIdx.y;
    if (v >= n) return;
    int lane = threadIdx.x;
    int g = lane >> 3, c = lane & 7;
    int beg = rs[v], end = rs[v + 1];
    float4 acc = row_sum4h(beg, end, csr_src, Tin, g, c);
    if (g == 0) {
        float r = 2.0f / lam[0];
        float dv = rsqrtf(fmaxf((float)__ldg(deg + v), 1.0f));
        float4 f4 = __ldg(f + (size_t)v * 8 + c);
        float4 x1;
        x1.x = -r * acc.x * dv + (r - 1.0f) * f4.x;
        x1.y = -r * acc.y * dv + (r - 1.0f) * f4.y;
        x1.z = -r * acc.z * dv + (r - 1.0f) * f4.z;
        x1.w = -r * acc.w * dv + (r - 1.0f) * f4.w;
        X1h[(size_t)v * 8 + c] = f4_to_h4(x1);
        float4 t;
        t.x = x1.x * dv; t.y = x1.y * dv; t.z = x1.z * dv; t.w = x1.w * dv;
        Tout[(size_t)v * 8 + c] = f4_to_h4(t);
    }
}

// Fused: acc = L-gather(T1h); X2 = -2r*acc*dv + 2(r-1)*X1 - f;
// out = leaky([X0,X1,X2] @ W + b); optional Tout_h = half(out*dinv)
__global__ void k_chebBL(const int* __restrict__ rs, const int* __restrict__ csr_src,
                         const uint2* __restrict__ Tin, const uint2* __restrict__ X1h,
                         const float4* __restrict__ f, const int* __restrict__ deg,
                         const float* __restrict__ lam, const float* __restrict__ W,
                         const float* __restrict__ b, float* __restrict__ out,
                         __half* __restrict__ Tout, int n) {
    __shared__ float sW[96 * 32];
    __shared__ float sb[32];
    __shared__ float sX[8][96];
    int t = threadIdx.y * 32 + threadIdx.x;
    for (int i = t; i < 96 * 32; i += 256) sW[i] = W[i];
    if (t < 32) sb[t] = b[t];
    __syncthreads();

    int v = blockIdx.x * 8 + threadIdx.y;
    if (v >= n) return;
    int lane = threadIdx.x;
    int g = lane >> 3, c = lane & 7;
    int beg = rs[v], end = rs[v + 1];
    float4 acc = row_sum4h(beg, end, csr_src, Tin, g, c);
    float dv = rsqrtf(fmaxf((float)__ldg(deg + v), 1.0f));
    if (g == 0) {
        float r = 2.0f / lam[0];
        float4 x1 = h4_to_f4(__ldg(X1h + (size_t)v * 8 + c));
        float4 f4 = __ldg(f + (size_t)v * 8 + c);
        float4 x2;
        x2.x = -2.0f * r * acc.x * dv + 2.0f * (r - 1.0f) * x1.x - f4.x;
        x2.y = -2.0f * r * acc.y * dv + 2.0f * (r - 1.0f) * x1.y - f4.y;
        x2.z = -2.0f * r * acc.z * dv + 2.0f * (r - 1.0f) * x1.z - f4.z;
        x2.w = -2.0f * r * acc.w * dv + 2.0f * (r - 1.0f) * x1.w - f4.w;
        float* sx = sX[threadIdx.y];
        sx[c * 4 + 0] = f4.x;  sx[c * 4 + 1] = f4.y;
        sx[c * 4 + 2] = f4.z;  sx[c * 4 + 3] = f4.w;
        sx[32 + c * 4 + 0] = x1.x;  sx[32 + c * 4 + 1] = x1.y;
        sx[32 + c * 4 + 2] = x1.z;  sx[32 + c * 4 + 3] = x1.w;
        sx[64 + c * 4 + 0] = x2.x;  sx[64 + c * 4 + 1] = x2.y;
        sx[64 + c * 4 + 2] = x2.z;  sx[64 + c * 4 + 3] = x2.w;
    }
    __syncwarp();
    const float* sx = sX[threadIdx.y];
    float s = sb[lane];
#pragma unroll
    for (int j = 0; j < 96; j++) s += sx[j] * sW[j * 32 + lane];
    s = leaky(s, 0.01f);
    out[(size_t)v * ND + lane] = s;
    if (Tout) Tout[(size_t)v * ND + lane] = __float2half(s * dv);
}

// fs_h = half(h@Ws+bs) ; fd_h = half(h@Wd+bd)
__global__ void k_fsfd(const float* __restrict__ h, const float* __restrict__ Ws,
                       const float* __restrict__ bs, const float* __restrict__ Wd,
                       const float* __restrict__ bd, __half* __restrict__ fsh,
                       __half* __restrict__ fdh, int n) {
    __shared__ float sWs[32 * 32], sWd[32 * 32], sbs[32], sbd[32];
    int t = threadIdx.y * 32 + threadIdx.x;
    for (int i = t; i < 1024; i += 256) { sWs[i] = Ws[i]; sWd[i] = Wd[i]; }
    if (t < 32) { sbs[t] = bs[t]; sbd[t] = bd[t]; }
    __syncthreads();
    int node = blockIdx.x * 8 + threadIdx.y;
    if (node >= n) return;
    int col = threadIdx.x;
    float a = sbs[col], c = sbd[col];
    const float* hr = h + (size_t)node * ND;
#pragma unroll
    for (int j = 0; j < 32; j++) {
        float x = hr[j];
        a += x * sWs[j * 32 + col];
        c += x * sWd[j * 32 + col];
    }
    fsh[(size_t)node * ND + col] = __float2half(a);
    fdh[(size_t)node * ND + col] = __float2half(c);
}

// ---------------------------------------------------------------------------
// fused GATv2: one CSR pass, plain softmax (shift-invariant; logits O(10)),
// 4 edges x 8 lanes per warp, fs/fd rows fp16. Re-zeros deg for next run.
// ---------------------------------------------------------------------------
__device__ __forceinline__ float edge_logit(float4 f0, float4 fd4, float4 w) {
    float t = leaky(f0.x + fd4.x, 0.2f) * w.x + leaky(f0.y + fd4.y, 0.2f) * w.y +
              leaky(f0.z + fd4.z, 0.2f) * w.z + leaky(f0.w + fd4.w, 0.2f) * w.w;
    t += __shfl_xor_sync(0xffffffffu, t, 1);
    t += __shfl_xor_sync(0xffffffffu, t, 2);
    t += __shfl_xor_sync(0xffffffffu, t, 4);
    return t;
}

__global__ void k_gat(const int* __restrict__ rs, const int* __restrict__ csr_src,
                      const uint2* __restrict__ fsh, const uint2* __restrict__ fdh,
                      const float4* __restrict__ attn, float4* __restrict__ out,
                      int* __restrict__ deg, int n) {
    int v = blockIdx.x * 8 + threadIdx.y;
    if (v >= n) return;
    int lane = threadIdx.x;
    int g = lane >> 3, c = lane & 7;
    int beg = rs[v], end = rs[v + 1];
    float4 fd4 = h4_to_f4(__ldg(fdh + (size_t)v * 8 + c));
    float4 w = __ldg(attn + c);
    float den = 0.0f;
    float4 acc = make_float4(0.f, 0.f, 0.f, 0.f);
    int base = beg;
    for (; base + 8 <= end; base += 8) {
        int s0 = __ldg(csr_src + base + g);
        int s1 = __ldg(csr_src + base + 4 + g);
        float4 f0 = h4_to_f4(__ldg(fsh + (size_t)s0 * 8 + c));
        float4 f1 = h4_to_f4(__ldg(fsh + (size_t)s1 * 8 + c));
        float t0 = edge_logit(f0, fd4, w);
        float t1 = edge_logit(f1, fd4, w);
        float e0 = __expf(t0);
        float e1 = __expf(t1);
        den += e0 + e1;
        acc.x += f0.x * e0 + f1.x * e1;
        acc.y += f0.y * e0 + f1.y * e1;
        acc.z += f0.z * e0 + f1.z * e1;
        acc.w += f0.w * e0 + f1.w * e1;
    }
    for (; base < end; base += 4) {
        int p = base + g;
        bool valid = p < end;
        int s0 = valid ? __ldg(csr_src + p) : 0;
        float4 f0 = h4_to_f4(__ldg(fsh + (size_t)s0 * 8 + c));
        float t0 = edge_logit(f0, fd4, w);  // all lanes participate in shfl
        if (valid) {
            float e0 = __expf(t0);
            den += e0;
            acc.x += f0.x * e0;
            acc.y += f0.y * e0;
            acc.z += f0.z * e0;
            acc.w += f0.w * e0;
        }
    }
#pragma unroll
    for (int o = 8; o <= 16; o <<= 1) {
        den   += __shfl_xor_sync(0xffffffffu, den,   o);
        acc.x += __shfl_xor_sync(0xffffffffu, acc.x, o);
        acc.y += __shfl_xor_sync(0xffffffffu, acc.y, o);
        acc.z += __shfl_xor_sync(0xffffffffu, acc.z, o);
        acc.w += __shfl_xor_sync(0xffffffffu, acc.w, o);
    }
    if (g == 0) {
        float inv = (den > 0.0f) ? 1.0f / den : 0.0f;
        float4 o;
        o.x = leaky(acc.x * inv, 0.01f);
        o.y = leaky(acc.y * inv, 0.01f);
        o.z = leaky(acc.z * inv, 0.01f);
        o.w = leaky(acc.w * inv, 0.01f);
        out[(size_t)v * 8 + c] = o;
        if (c == 0) deg[v] = 0;  // ready for next run / replay
    }
}

// ---------------------------------------------------------------------------
// launch
// ---------------------------------------------------------------------------
extern "C" void kernel_launch(void* const* d_in, const int* in_sizes, int n_in,
                              void* d_out, int out_size) {
    const int*   src  = (const int*)d_in[0];
    const int*   dst  = (const int*)d_in[1];
    const float* emb  = (const float*)d_in[2];
    const float* lam  = (const float*)d_in[3];
    const float* chW  = (const float*)d_in[4];
    const float* chb  = (const float*)d_in[5];
    const float* Ws   = (const float*)d_in[6];
    const float* bs   = (const float*)d_in[7];
    const float* Wd   = (const float*)d_in[8];
    const float* bd   = (const float*)d_in[9];
    const float* attn = (const float*)d_in[10];

    const int E = in_sizes[0];
    const int n = in_sizes[2] / ND;

    float* base = nullptr;
    cudaGetSymbolAddress((void**)&base, g_buf);

    float*  h1      = base;
    float*  h2      = base + 1 * SLOT;
    __half* T0h     = (__half*)(base + 2 * SLOT);
    __half* T1h     = (__half*)(base + 2 * SLOT + SLOT / 2);
    __half* X1h     = (__half*)(base + 3 * SLOT);
    __half* fsh     = (__half*)(base + 3 * SLOT + SLOT / 2);
    __half* fdh     = (__half*)(base + 4 * SLOT);
    int*    csr_src = (int*)(base + 5 * SLOT);
    float*  tail    = base + 5 * SLOT + MAXE;
    int*    deg     = (int*)tail;
    int*    rs      = (int*)(tail + MAXN);          // N+1
    int*    cursor  = (int*)(tail + 2 * MAXN + 64);
    int*    blk     = (int*)(tail + 3 * MAXN + 64);

    const int nt = 256;
    auto g = [&](long x) { return (int)((x + nt - 1) / nt); };
    const int gV4   = g((long)n * 8);
    const int gEdge = g((long)E);
    const int gNW   = (n + 7) / 8;
    dim3 bNW(32, 8);
    const int nb = (n + 1023) / 1024;

    // --- CSR build (deg already zero: static init / re-zeroed by k_gat) ---
    k_deg<<<gEdge, nt>>>(dst, deg, E);
    k_scan1<<<nb, 1024>>>(deg, rs, blk, n);
    k_scan2<<<1, 128>>>(blk, nb);
    k_scan3p<<<gV4, nt>>>(rs, cursor, blk, deg, (const float4*)emb, (uint2*)T0h, n, E);
    k_fill<<<gEdge, nt>>>(src, dst, cursor, csr_src, E);

    // --- ChebConv 1 (input = embedding) ---
    k_chebA<<<gNW, bNW>>>(rs, csr_src, (const uint2*)T0h, (const float4*)emb,
                          deg, lam, (uint2*)X1h, (uint2*)T1h, n);
    k_chebBL<<<gNW, bNW>>>(rs, csr_src, (const uint2*)T1h, (const uint2*)X1h,
                           (const float4*)emb, deg, lam, chW, chb, h1, T0h, n);

    // --- ChebConv 2 (input = h1; T0h = h1*dinv) ---
    k_chebA<<<gNW, bNW>>>(rs, csr_src, (const uint2*)T0h, (const float4*)h1,
                          deg, lam, (uint2*)X1h, (uint2*)T1h, n);
    k_chebBL<<<gNW, bNW>>>(rs, csr_src, (const uint2*)T1h, (const uint2*)X1h,
                           (const float4*)h1, deg, lam, chW, chb, h2, nullptr, n);

    // --- GATv2 (fused single pass, fp16 fs/fd, plain softmax) ---
    k_fsfd<<<gNW, bNW>>>(h2, Ws, bs, Wd, bd, fsh, fdh, n);
    k_gat<<<gNW, bNW>>>(rs, csr_src, (const uint2*)fsh, (const uint2*)fdh,
                        (const float4*)attn, (float4*)d_out, deg, n);
}

// round 14
// speedup vs baseline: 1.3028x; 1.1538x over previous
#include <cuda_runtime.h>
#include <cuda_fp16.h>

#define ND 32
#define MAXN 100000
#define MAXE 1600000

static constexpr size_t SLOT = (size_t)MAXN * ND;

// Scratch arena (floats):
//  h1,h2 : 2 * SLOT fp32
//  T0h,T1h,X1h,fsh,fdh : 5 * SLOT/2 (fp16 rows)
//  csr_src : MAXE int
//  tail: deg(N), rs(N+1), cursor(N), blk(128)
__device__ __align__(256) float g_buf[5 * SLOT + (size_t)MAXE + 6 * (size_t)MAXN + 2048];

__device__ __forceinline__ float leaky(float x, float s) {
    return x > 0.0f ? x : s * x;
}
__device__ __forceinline__ uint2 f4_to_h4(float4 v) {
    __half2 a = __floats2half2_rn(v.x, v.y);
    __half2 b = __floats2half2_rn(v.z, v.w);
    uint2 r;
    r.x = *(unsigned*)&a;
    r.y = *(unsigned*)&b;
    return r;
}
__device__ __forceinline__ float4 h4_to_f4(uint2 u) {
    __half2 a = *(__half2*)&u.x;
    __half2 b = *(__half2*)&u.y;
    float2 fa = __half22float2(a), fb = __half22float2(b);
    return make_float4(fa.x, fa.y, fb.x, fb.y);
}

// ---------------------------------------------------------------------------
// degree + scan + CSR fill  (deg zeroed by k_gat at end of previous run;
// static zero-init covers the first call)
// ---------------------------------------------------------------------------
__global__ void k_deg(const int* __restrict__ dst, int* __restrict__ deg, int E) {
    int e = blockIdx.x * blockDim.x + threadIdx.x;
    if (e < E) atomicAdd(&deg[dst[e]], 1);
}

__global__ void k_scan1(const int* __restrict__ deg, int* __restrict__ rs,
                        int* __restrict__ blk, int n) {
    __shared__ int sh[1024];
    int i = blockIdx.x * 1024 + threadIdx.x;
    int v = (i < n) ? deg[i] : 0;
    sh[threadIdx.x] = v;
    __syncthreads();
#pragma unroll
    for (int o = 1; o < 1024; o <<= 1) {
        int t = (threadIdx.x >= o) ? sh[threadIdx.x - o] : 0;
        __syncthreads();
        sh[threadIdx.x] += t;
        __syncthreads();
    }
    if (i < n) rs[i] = sh[threadIdx.x] - v;
    if (threadIdx.x == 1023) blk[blockIdx.x] = sh[1023];
}

__global__ void k_scan2(int* __restrict__ blk, int nb) {
    __shared__ int sh[128];
    int t = threadIdx.x;
    int v = (t < nb) ? blk[t] : 0;
    sh[t] = v;
    __syncthreads();
#pragma unroll
    for (int o = 1; o < 128; o <<= 1) {
        int x = (t >= o) ? sh[t - o] : 0;
        __syncthreads();
        sh[t] += x;
        __syncthreads();
    }
    if (t < nb) blk[t] = sh[t] - v;
}

// finalize row starts + cursors; also T0h = half(emb * dinv)  (fused prescale)
__global__ void k_scan3p(int* __restrict__ rs, int* __restrict__ cursor,
                         const int* __restrict__ blk, const int* __restrict__ deg,
                         const float4* __restrict__ emb, uint2* __restrict__ T0h,
                         int n, int E) {
    int i = blockIdx.x * blockDim.x + threadIdx.x;
    if (i >= n * 8) return;
    int node = i >> 3;
    float dv = rsqrtf(fmaxf((float)__ldg(deg + node), 1.0f));
    float4 v = __ldg(emb + i);
    v.x *= dv; v.y *= dv; v.z *= dv; v.w *= dv;
    T0h[i] = f4_to_h4(v);
    if ((i & 7) == 0) {
        int p = rs[node] + blk[node >> 10];
        rs[node] = p;
        cursor[node] = p;
        if (node == 0) rs[n] = E;
    }
}

__global__ void k_fill(const int* __restrict__ src, const int* __restrict__ dst,
                       int* __restrict__ cursor, int* __restrict__ csr_src, int E) {
    int e = blockIdx.x * blockDim.x + threadIdx.x;
    if (e >= E) return;
    int p = atomicAdd(&cursor[dst[e]], 1);
    csr_src[p] = src[e];
}

// ---------------------------------------------------------------------------
// warp-per-node CSR row sum over fp16 rows: 4 edges x 8 lanes (uint2/lane),
// up to 4 rows in flight per group. fp32 accum.
// ---------------------------------------------------------------------------
__device__ __forceinline__ float4 row_sum4h(int beg, int end,
                                            const int* __restrict__ csr_src,
                                            const uint2* __restrict__ Th,
                                            int g, int c) {
    float4 acc = make_float4(0.f, 0.f, 0.f, 0.f);
    int base = beg;
    for (; base + 16 <= end; base += 16) {
        int i0 = __ldg(csr_src + base + g);
        int i1 = __ldg(csr_src + base + 4 + g);
        int i2 = __ldg(csr_src + base + 8 + g);
        int i3 = __ldg(csr_src + base + 12 + g);
        float4 v0 = h4_to_f4(__ldg(Th + (size_t)i0 * 8 + c));
        float4 v1 = h4_to_f4(__ldg(Th + (size_t)i1 * 8 + c));
        float4 v2 = h4_to_f4(__ldg(Th + (size_t)i2 * 8 + c));
        float4 v3 = h4_to_f4(__ldg(Th + (size_t)i3 * 8 + c));
        acc.x += (v0.x + v1.x) + (v2.x + v3.x);
        acc.y += (v0.y + v1.y) + (v2.y + v3.y);
        acc.z += (v0.z + v1.z) + (v2.z + v3.z);
        acc.w += (v0.w + v1.w) + (v2.w + v3.w);
    }
    for (; base + 8 <= end; base += 8) {
        int i0 = __ldg(csr_src + base + g);
        int i1 = __ldg(csr_src + base + 4 + g);
        float4 v0 = h4_to_f4(__ldg(Th + (size_t)i0 * 8 + c));
        float4 v1 = h4_to_f4(__ldg(Th + (size_t)i1 * 8 + c));
        acc.x += v0.x + v1.x;
        acc.y += v0.y + v1.y;
        acc.z += v0.z + v1.z;
        acc.w += v0.w + v1.w;
    }
    for (; base < end; base += 4) {
        int p = base + g;
        if (p < end) {
            int i0 = __ldg(csr_src + p);
            float4 v0 = h4_to_f4(__ldg(Th + (size_t)i0 * 8 + c));
            acc.x += v0.x; acc.y += v0.y; acc.z += v0.z; acc.w += v0.w;
        }
    }
#pragma unroll
    for (int o = 8; o <= 16; o <<= 1) {
        acc.x += __shfl_xor_sync(0xffffffffu, acc.x, o);
        acc.y += __shfl_xor_sync(0xffffffffu, acc.y, o);
        acc.z += __shfl_xor_sync(0xffffffffu, acc.z, o);
        acc.w += __shfl_xor_sync(0xffffffffu, acc.w, o);
    }
    return acc;
}

// X1h = half(-r*acc*dv + (r-1)*f); T1h = half(X1*dv)
__global__ void k_chebA(const int* __restrict__ rs, const int* __restrict__ csr_src,
                        const uint2* __restrict__ Tin, const float4* __restrict__ f,
                        const int* __restrict__ deg, const float* __restrict__ lam,
                        uint2* __restrict__ X1h, uint2* __restrict__ Tout, int n) {
    int v = blockIdx.x * 8 + threadIdx.y;
    if (v >= n) return;
    int lane = threadIdx.x;
    int g = lane >> 3, c = lane & 7;
    int beg = rs[v], end = rs[v + 1];
    float4 acc = row_sum4h(beg, end, csr_src, Tin, g, c);
    if (g == 0) {
        float r = 2.0f / lam[0];
        float dv = rsqrtf(fmaxf((float)__ldg(deg + v), 1.0f));
        float4 f4 = __ldg(f + (size_t)v * 8 + c);
        float4 x1;
        x1.x = -r * acc.x * dv + (r - 1.0f) * f4.x;
        x1.y = -r * acc.y * dv + (r - 1.0f) * f4.y;
        x1.z = -r * acc.z * dv + (r - 1.0f) * f4.z;
        x1.w = -r * acc.w * dv + (r - 1.0f) * f4.w;
        X1h[(size_t)v * 8 + c] = f4_to_h4(x1);
        float4 t;
        t.x = x1.x * dv; t.y = x1.y * dv; t.z = x1.z * dv; t.w = x1.w * dv;
        Tout[(size_t)v * 8 + c] = f4_to_h4(t);
    }
}

// Fused: acc = L-gather(T1h); X2 = -2r*acc*dv + 2(r-1)*X1 - f;
// out = leaky([X0,X1,X2] @ W + b); optional Tout_h = half(out*dinv)
// Weights staged in shared as half2 pairs: 48 j-pairs, crossbar traffic ~4x less.
__global__ void k_chebBL(const int* __restrict__ rs, const int* __restrict__ csr_src,
                         const uint2* __restrict__ Tin, const uint2* __restrict__ X1h,
                         const float4* __restrict__ f, const int* __restrict__ deg,
                         const float* __restrict__ lam, const float* __restrict__ W,
                         const float* __restrict__ b, float* __restrict__ out,
                         __half* __restrict__ Tout, int n) {
    __shared__ __half2 sW2[48 * 32];  // sW2[j2*32+col] = (W[2j2][col], W[2j2+1][col])
    __shared__ float sb[32];
    __shared__ float sX[8][96];
    int t = threadIdx.y * 32 + threadIdx.x;
    for (int i = t; i < 48 * 32; i += 256) {
        int j2 = i >> 5, col = i & 31;
        sW2[i] = __floats2half2_rn(W[(2 * j2) * 32 + col], W[(2 * j2 + 1) * 32 + col]);
    }
    if (t < 32) sb[t] = b[t];
    __syncthreads();

    int v = blockIdx.x * 8 + threadIdx.y;
    if (v >= n) return;
    int lane = threadIdx.x;
    int g = lane >> 3, c = lane & 7;
    int beg = rs[v], end = rs[v + 1];
    float4 acc = row_sum4h(beg, end, csr_src, Tin, g, c);
    float dv = rsqrtf(fmaxf((float)__ldg(deg + v), 1.0f));
    if (g == 0) {
        float r = 2.0f / lam[0];
        float4 x1 = h4_to_f4(__ldg(X1h + (size_t)v * 8 + c));
        float4 f4 = __ldg(f + (size_t)v * 8 + c);
        float4 x2;
        x2.x = -2.0f * r * acc.x * dv + 2.0f * (r - 1.0f) * x1.x - f4.x;
        x2.y = -2.0f * r * acc.y * dv + 2.0f * (r - 1.0f) * x1.y - f4.y;
        x2.z = -2.0f * r * acc.z * dv + 2.0f * (r - 1.0f) * x1.z - f4.z;
        x2.w = -2.0f * r * acc.w * dv + 2.0f * (r - 1.0f) * x1.w - f4.w;
        float* sx = sX[threadIdx.y];
        sx[c * 4 + 0] = f4.x;  sx[c * 4 + 1] = f4.y;
        sx[c * 4 + 2] = f4.z;  sx[c * 4 + 3] = f4.w;
        sx[32 + c * 4 + 0] = x1.x;  sx[32 + c * 4 + 1] = x1.y;
        sx[32 + c * 4 + 2] = x1.z;  sx[32 + c * 4 + 3] = x1.w;
        sx[64 + c * 4 + 0] = x2.x;  sx[64 + c * 4 + 1] = x2.y;
        sx[64 + c * 4 + 2] = x2.z;  sx[64 + c * 4 + 3] = x2.w;
    }
    __syncwarp();
    const float2* sx2 = (const float2*)sX[threadIdx.y];
    float s = sb[lane];
#pragma unroll
    for (int j2 = 0; j2 < 48; j2++) {
        float2 x = sx2[j2];                       // broadcast, 8 B/warp
        float2 w = __half22float2(sW2[j2 * 32 + lane]);  // 64 B/warp
        s += x.x * w.x + x.y * w.y;
    }
    s = leaky(s, 0.01f);
    out[(size_t)v * ND + lane] = s;
    if (Tout) Tout[(size_t)v * ND + lane] = __float2half(s * dv);
}

// fs_h = half(h@Ws+bs) ; fd_h = half(h@Wd+bd)  — weights staged as half2
__global__ void k_fsfd(const float* __restrict__ h, const float* __restrict__ Ws,
                       const float* __restrict__ bs, const float* __restrict__ Wd,
                       const float* __restrict__ bd, __half* __restrict__ fsh,
                       __half* __restrict__ fdh, int n) {
    __shared__ __half2 sWs2[16 * 32], sWd2[16 * 32];
    __shared__ float sbs[32], sbd[32];
    int t = threadIdx.y * 32 + threadIdx.x;
    for (int i = t; i < 16 * 32; i += 256) {
        int j2 = i >> 5, col = i & 31;
        sWs2[i] = __floats2half2_rn(Ws[(2 * j2) * 32 + col], Ws[(2 * j2 + 1) * 32 + col]);
        sWd2[i] = __floats2half2_rn(Wd[(2 * j2) * 32 + col], Wd[(2 * j2 + 1) * 32 + col]);
    }
    if (t < 32) { sbs[t] = bs[t]; sbd[t] = bd[t]; }
    __syncthreads();
    int node = blockIdx.x * 8 + threadIdx.y;
    if (node >= n) return;
    int col = threadIdx.x;
    float a = sbs[col], c = sbd[col];
    const float2* hr2 = (const float2*)(h + (size_t)node * ND);
#pragma unroll
    for (int j2 = 0; j2 < 16; j2++) {
        float2 x = __ldg(hr2 + j2);
        float2 ws = __half22float2(sWs2[j2 * 32 + col]);
        float2 wd = __half22float2(sWd2[j2 * 32 + col]);
        a += x.x * ws.x + x.y * ws.y;
        c += x.x * wd.x + x.y * wd.y;
    }
    fsh[(size_t)node * ND + col] = __float2half(a);
    fdh[(size_t)node * ND + col] = __float2half(c);
}

// ---------------------------------------------------------------------------
// fused GATv2: one CSR pass, plain softmax (shift-invariant; logits O(10)),
// 4 edges x 8 lanes per warp, fs/fd rows fp16. Re-zeros deg for next run.
// ---------------------------------------------------------------------------
__device__ __forceinline__ float edge_logit(float4 f0, float4 fd4, float4 w) {
    float t = leaky(f0.x + fd4.x, 0.2f) * w.x + leaky(f0.y + fd4.y, 0.2f) * w.y +
              leaky(f0.z + fd4.z, 0.2f) * w.z + leaky(f0.w + fd4.w, 0.2f) * w.w;
    t += __shfl_xor_sync(0xffffffffu, t, 1);
    t += __shfl_xor_sync(0xffffffffu, t, 2);
    t += __shfl_xor_sync(0xffffffffu, t, 4);
    return t;
}

__global__ void k_gat(const int* __restrict__ rs, const int* __restrict__ csr_src,
                      const uint2* __restrict__ fsh, const uint2* __restrict__ fdh,
                      const float4* __restrict__ attn, float4* __restrict__ out,
                      int* __restrict__ deg, int n) {
    int v = blockIdx.x * 8 + threadIdx.y;
    if (v >= n) return;
    int lane = threadIdx.x;
    int g = lane >> 3, c = lane & 7;
    int beg = rs[v], end = rs[v + 1];
    float4 fd4 = h4_to_f4(__ldg(fdh + (size_t)v * 8 + c));
    float4 w = __ldg(attn + c);
    float den = 0.0f;
    float4 acc = make_float4(0.f, 0.f, 0.f, 0.f);
    int base = beg;
    for (; base + 8 <= end; base += 8) {
        int s0 = __ldg(csr_src + base + g);
        int s1 = __ldg(csr_src + base + 4 + g);
        float4 f0 = h4_to_f4(__ldg(fsh + (size_t)s0 * 8 + c));
        float4 f1 = h4_to_f4(__ldg(fsh + (size_t)s1 * 8 + c));
        float t0 = edge_logit(f0, fd4, w);
        float t1 = edge_logit(f1, fd4, w);
        float e0 = __expf(t0);
        float e1 = __expf(t1);
        den += e0 + e1;
        acc.x += f0.x * e0 + f1.x * e1;
        acc.y += f0.y * e0 + f1.y * e1;
        acc.z += f0.z * e0 + f1.z * e1;
        acc.w += f0.w * e0 + f1.w * e1;
    }
    for (; base < end; base += 4) {
        int p = base + g;
        bool valid = p < end;
        int s0 = valid ? __ldg(csr_src + p) : 0;
        float4 f0 = h4_to_f4(__ldg(fsh + (size_t)s0 * 8 + c));
        float t0 = edge_logit(f0, fd4, w);  // all lanes participate in shfl
        if (valid) {
            float e0 = __expf(t0);
            den += e0;
            acc.x += f0.x * e0;
            acc.y += f0.y * e0;
            acc.z += f0.z * e0;
            acc.w += f0.w * e0;
        }
    }
#pragma unroll
    for (int o = 8; o <= 16; o <<= 1) {
        den   += __shfl_xor_sync(0xffffffffu, den,   o);
        acc.x += __shfl_xor_sync(0xffffffffu, acc.x, o);
        acc.y += __shfl_xor_sync(0xffffffffu, acc.y, o);
        acc.z += __shfl_xor_sync(0xffffffffu, acc.z, o);
        acc.w += __shfl_xor_sync(0xffffffffu, acc.w, o);
    }
    if (g == 0) {
        float inv = (den > 0.0f) ? 1.0f / den : 0.0f;
        float4 o;
        o.x = leaky(acc.x * inv, 0.01f);
        o.y = leaky(acc.y * inv, 0.01f);
        o.z = leaky(acc.z * inv, 0.01f);
        o.w = leaky(acc.w * inv, 0.01f);
        out[(size_t)v * 8 + c] = o;
        if (c == 0) deg[v] = 0;  // ready for next run / replay
    }
}

// ---------------------------------------------------------------------------
// launch
// ---------------------------------------------------------------------------
extern "C" void kernel_launch(void* const* d_in, const int* in_sizes, int n_in,
                              void* d_out, int out_size) {
    const int*   src  = (const int*)d_in[0];
    const int*   dst  = (const int*)d_in[1];
    const float* emb  = (const float*)d_in[2];
    const float* lam  = (const float*)d_in[3];
    const float* chW  = (const float*)d_in[4];
    const float* chb  = (const float*)d_in[5];
    const float* Ws   = (const float*)d_in[6];
    const float* bs   = (const float*)d_in[7];
    const float* Wd   = (const float*)d_in[8];
    const float* bd   = (const float*)d_in[9];
    const float* attn = (const float*)d_in[10];

    const int E = in_sizes[0];
    const int n = in_sizes[2] / ND;

    float* base = nullptr;
    cudaGetSymbolAddress((void**)&base, g_buf);

    float*  h1      = base;
    float*  h2      = base + 1 * SLOT;
    __half* T0h     = (__half*)(base + 2 * SLOT);
    __half* T1h     = (__half*)(base + 2 * SLOT + SLOT / 2);
    __half* X1h     = (__half*)(base + 3 * SLOT);
    __half* fsh     = (__half*)(base + 3 * SLOT + SLOT / 2);
    __half* fdh     = (__half*)(base + 4 * SLOT);
    int*    csr_src = (int*)(base + 5 * SLOT);
    float*  tail    = base + 5 * SLOT + MAXE;
    int*    deg     = (int*)tail;
    int*    rs      = (int*)(tail + MAXN);          // N+1
    int*    cursor  = (int*)(tail + 2 * MAXN + 64);
    int*    blk     = (int*)(tail + 3 * MAXN + 64);

    const int nt = 256;
    auto g = [&](long x) { return (int)((x + nt - 1) / nt); };
    const int gV4   = g((long)n * 8);
    const int gEdge = g((long)E);
    const int gNW   = (n + 7) / 8;
    dim3 bNW(32, 8);
    const int nb = (n + 1023) / 1024;

    // --- CSR build (deg already zero: static init / re-zeroed by k_gat) ---
    k_deg<<<gEdge, nt>>>(dst, deg, E);
    k_scan1<<<nb, 1024>>>(deg, rs, blk, n);
    k_scan2<<<1, 128>>>(blk, nb);
    k_scan3p<<<gV4, nt>>>(rs, cursor, blk, deg, (const float4*)emb, (uint2*)T0h, n, E);
    k_fill<<<gEdge, nt>>>(src, dst, cursor, csr_src, E);

    // --- ChebConv 1 (input = embedding) ---
    k_chebA<<<gNW, bNW>>>(rs, csr_src, (const uint2*)T0h, (const float4*)emb,
                          deg, lam, (uint2*)X1h, (uint2*)T1h, n);
    k_chebBL<<<gNW, bNW>>>(rs, csr_src, (const uint2*)T1h, (const uint2*)X1h,
                           (const float4*)emb, deg, lam, chW, chb, h1, T0h, n);

    // --- ChebConv 2 (input = h1; T0h = h1*dinv) ---
    k_chebA<<<gNW, bNW>>>(rs, csr_src, (const uint2*)T0h, (const float4*)h1,
                          deg, lam, (uint2*)X1h, (uint2*)T1h, n);
    k_chebBL<<<gNW, bNW>>>(rs, csr_src, (const uint2*)T1h, (const uint2*)X1h,
                           (const float4*)h1, deg, lam, chW, chb, h2, nullptr, n);

    // --- GATv2 (fused single pass, fp16 fs/fd, plain softmax) ---
    k_fsfd<<<gNW, bNW>>>(h2, Ws, bs, Wd, bd, fsh, fdh, n);
    k_gat<<<gNW, bNW>>>(rs, csr_src, (const uint2*)fsh, (const uint2*)fdh,
                        (const float4*)attn, (float4*)d_out, deg, n);
}

// round 15
// speedup vs baseline: 1.3481x; 1.0348x over previous
#include <cuda_runtime.h>
#include <cuda_fp16.h>

#define ND 32
#define MAXN 100000
#define MAXE 1600000

static constexpr size_t SLOT = (size_t)MAXN * ND;

// Scratch arena (floats):
//  h1 : SLOT fp32
//  T0h,T1h,X1h,fsh,fdh : 5 * SLOT/2 (fp16 rows)
//  csr_src : MAXE int
//  tail: deg(N), rs(N+1), cursor(N), blk(128)
__device__ __align__(256) float g_buf[4 * SLOT + (size_t)MAXE + 6 * (size_t)MAXN + 2048];

__device__ __forceinline__ float leaky(float x, float s) {
    return x > 0.0f ? x : s * x;
}
__device__ __forceinline__ uint2 f4_to_h4(float4 v) {
    __half2 a = __floats2half2_rn(v.x, v.y);
    __half2 b = __floats2half2_rn(v.z, v.w);
    uint2 r;
    r.x = *(unsigned*)&a;
    r.y = *(unsigned*)&b;
    return r;
}
__device__ __forceinline__ float4 h4_to_f4(uint2 u) {
    __half2 a = *(__half2*)&u.x;
    __half2 b = *(__half2*)&u.y;
    float2 fa = __half22float2(a), fb = __half22float2(b);
    return make_float4(fa.x, fa.y, fb.x, fb.y);
}

// ---------------------------------------------------------------------------
// degree + scan + CSR fill  (deg zeroed by k_gat at end of previous run;
// static zero-init covers the first call)
// ---------------------------------------------------------------------------
__global__ void k_deg(const int* __restrict__ dst, int* __restrict__ deg, int E) {
    int e = blockIdx.x * blockDim.x + threadIdx.x;
    if (e < E) atomicAdd(&deg[dst[e]], 1);
}

__global__ void k_scan1(const int* __restrict__ deg, int* __restrict__ rs,
                        int* __restrict__ blk, int n) {
    __shared__ int sh[1024];
    int i = blockIdx.x * 1024 + threadIdx.x;
    int v = (i < n) ? deg[i] : 0;
    sh[threadIdx.x] = v;
    __syncthreads();
#pragma unroll
    for (int o = 1; o < 1024; o <<= 1) {
        int t = (threadIdx.x >= o) ? sh[threadIdx.x - o] : 0;
        __syncthreads();
        sh[threadIdx.x] += t;
        __syncthreads();
    }
    if (i < n) rs[i] = sh[threadIdx.x] - v;
    if (threadIdx.x == 1023) blk[blockIdx.x] = sh[1023];
}

__global__ void k_scan2(int* __restrict__ blk, int nb) {
    __shared__ int sh[128];
    int t = threadIdx.x;
    int v = (t < nb) ? blk[t] : 0;
    sh[t] = v;
    __syncthreads();
#pragma unroll
    for (int o = 1; o < 128; o <<= 1) {
        int x = (t >= o) ? sh[t - o] : 0;
        __syncthreads();
        sh[t] += x;
        __syncthreads();
    }
    if (t < nb) blk[t] = sh[t] - v;
}

// finalize row starts + cursors; also T0h = half(emb * dinv)  (fused prescale)
__global__ void k_scan3p(int* __restrict__ rs, int* __restrict__ cursor,
                         const int* __restrict__ blk, const int* __restrict__ deg,
                         const float4* __restrict__ emb, uint2* __restrict__ T0h,
                         int n, int E) {
    int i = blockIdx.x * blockDim.x + threadIdx.x;
    if (i >= n * 8) return;
    int node = i >> 3;
    float dv = rsqrtf(fmaxf((float)__ldg(deg + node), 1.0f));
    float4 v = __ldg(emb + i);
    v.x *= dv; v.y *= dv; v.z *= dv; v.w *= dv;
    T0h[i] = f4_to_h4(v);
    if ((i & 7) == 0) {
        int p = rs[node] + blk[node >> 10];
        rs[node] = p;
        cursor[node] = p;
        if (node == 0) rs[n] = E;
    }
}

__global__ void k_fill(const int* __restrict__ src, const int* __restrict__ dst,
                       int* __restrict__ cursor, int* __restrict__ csr_src, int E) {
    int e = blockIdx.x * blockDim.x + threadIdx.x;
    if (e >= E) return;
    int p = atomicAdd(&cursor[dst[e]], 1);
    csr_src[p] = src[e];
}

// ---------------------------------------------------------------------------
// warp-per-node CSR row sum over fp16 rows: 4 edges x 8 lanes (uint2/lane),
// up to 4 rows in flight per group. fp32 accum.
// ---------------------------------------------------------------------------
__device__ __forceinline__ float4 row_sum4h(int beg, int end,
                                            const int* __restrict__ csr_src,
                                            const uint2* __restrict__ Th,
                                            int g, int c) {
    float4 acc = make_float4(0.f, 0.f, 0.f, 0.f);
    int base = beg;
    for (; base + 16 <= end; base += 16) {
        int i0 = __ldg(csr_src + base + g);
        int i1 = __ldg(csr_src + base + 4 + g);
        int i2 = __ldg(csr_src + base + 8 + g);
        int i3 = __ldg(csr_src + base + 12 + g);
        float4 v0 = h4_to_f4(__ldg(Th + (size_t)i0 * 8 + c));
        float4 v1 = h4_to_f4(__ldg(Th + (size_t)i1 * 8 + c));
        float4 v2 = h4_to_f4(__ldg(Th + (size_t)i2 * 8 + c));
        float4 v3 = h4_to_f4(__ldg(Th + (size_t)i3 * 8 + c));
        acc.x += (v0.x + v1.x) + (v2.x + v3.x);
        acc.y += (v0.y + v1.y) + (v2.y + v3.y);
        acc.z += (v0.z + v1.z) + (v2.z + v3.z);
        acc.w += (v0.w + v1.w) + (v2.w + v3.w);
    }
    for (; base + 8 <= end; base += 8) {
        int i0 = __ldg(csr_src + base + g);
        int i1 = __ldg(csr_src + base + 4 + g);
        float4 v0 = h4_to_f4(__ldg(Th + (size_t)i0 * 8 + c));
        float4 v1 = h4_to_f4(__ldg(Th + (size_t)i1 * 8 + c));
        acc.x += v0.x + v1.x;
        acc.y += v0.y + v1.y;
        acc.z += v0.z + v1.z;
        acc.w += v0.w + v1.w;
    }
    for (; base < end; base += 4) {
        int p = base + g;
        if (p < end) {
            int i0 = __ldg(csr_src + p);
            float4 v0 = h4_to_f4(__ldg(Th + (size_t)i0 * 8 + c));
            acc.x += v0.x; acc.y += v0.y; acc.z += v0.z; acc.w += v0.w;
        }
    }
#pragma unroll
    for (int o = 8; o <= 16; o <<= 1) {
        acc.x += __shfl_xor_sync(0xffffffffu, acc.x, o);
        acc.y += __shfl_xor_sync(0xffffffffu, acc.y, o);
        acc.z += __shfl_xor_sync(0xffffffffu, acc.z, o);
        acc.w += __shfl_xor_sync(0xffffffffu, acc.w, o);
    }
    return acc;
}

// X1h = half(-r*acc*dv + (r-1)*f); T1h = half(X1*dv)
__global__ void k_chebA(const int* __restrict__ rs, const int* __restrict__ csr_src,
                        const uint2* __restrict__ Tin, const float4* __restrict__ f,
                        const int* __restrict__ deg, const float* __restrict__ lam,
                        uint2* __restrict__ X1h, uint2* __restrict__ Tout, int n) {
    int v = blockIdx.x * 8 + threadIdx.y;
    if (v >= n) return;
    int lane = threadIdx.x;
    int g = lane >> 3, c = lane & 7;
    int beg = rs[v], end = rs[v + 1];
    float4 acc = row_sum4h(beg, end, csr_src, Tin, g, c);
    if (g == 0) {
        float r = 2.0f / lam[0];
        float dv = rsqrtf(fmaxf((float)__ldg(deg + v), 1.0f));
        float4 f4 = __ldg(f + (size_t)v * 8 + c);
        float4 x1;
        x1.x = -r * acc.x * dv + (r - 1.0f) * f4.x;
        x1.y = -r * acc.y * dv + (r - 1.0f) * f4.y;
        x1.z = -r * acc.z * dv + (r - 1.0f) * f4.z;
        x1.w = -r * acc.w * dv + (r - 1.0f) * f4.w;
        X1h[(size_t)v * 8 + c] = f4_to_h4(x1);
        float4 t;
        t.x = x1.x * dv; t.y = x1.y * dv; t.z = x1.z * dv; t.w = x1.w * dv;
        Tout[(size_t)v * 8 + c] = f4_to_h4(t);
    }
}

// Fused: acc = L-gather(T1h); X2 = -2r*acc*dv + 2(r-1)*X1 - f;
// out = leaky([X0,X1,X2] @ W + b); Tout_h = half(out*dinv)
// Weights staged in shared as half2 pairs.
__global__ void k_chebBL(const int* __restrict__ rs, const int* __restrict__ csr_src,
                         const uint2* __restrict__ Tin, const uint2* __restrict__ X1h,
                         const float4* __restrict__ f, const int* __restrict__ deg,
                         const float* __restrict__ lam, const float* __restrict__ W,
                         const float* __restrict__ b, float* __restrict__ out,
                         __half* __restrict__ Tout, int n) {
    __shared__ __half2 sW2[48 * 32];
    __shared__ float sb[32];
    __shared__ float sX[8][96];
    int t = threadIdx.y * 32 + threadIdx.x;
    for (int i = t; i < 48 * 32; i += 256) {
        int j2 = i >> 5, col = i & 31;
        sW2[i] = __floats2half2_rn(W[(2 * j2) * 32 + col], W[(2 * j2 + 1) * 32 + col]);
    }
    if (t < 32) sb[t] = b[t];
    __syncthreads();

    int v = blockIdx.x * 8 + threadIdx.y;
    if (v >= n) return;
    int lane = threadIdx.x;
    int g = lane >> 3, c = lane & 7;
    int beg = rs[v], end = rs[v + 1];
    float4 acc = row_sum4h(beg, end, csr_src, Tin, g, c);
    float dv = rsqrtf(fmaxf((float)__ldg(deg + v), 1.0f));
    if (g == 0) {
        float r = 2.0f / lam[0];
        float4 x1 = h4_to_f4(__ldg(X1h + (size_t)v * 8 + c));
        float4 f4 = __ldg(f + (size_t)v * 8 + c);
        float4 x2;
        x2.x = -2.0f * r * acc.x * dv + 2.0f * (r - 1.0f) * x1.x - f4.x;
        x2.y = -2.0f * r * acc.y * dv + 2.0f * (r - 1.0f) * x1.y - f4.y;
        x2.z = -2.0f * r * acc.z * dv + 2.0f * (r - 1.0f) * x1.z - f4.z;
        x2.w = -2.0f * r * acc.w * dv + 2.0f * (r - 1.0f) * x1.w - f4.w;
        float* sx = sX[threadIdx.y];
        sx[c * 4 + 0] = f4.x;  sx[c * 4 + 1] = f4.y;
        sx[c * 4 + 2] = f4.z;  sx[c * 4 + 3] = f4.w;
        sx[32 + c * 4 + 0] = x1.x;  sx[32 + c * 4 + 1] = x1.y;
        sx[32 + c * 4 + 2] = x1.z;  sx[32 + c * 4 + 3] = x1.w;
        sx[64 + c * 4 + 0] = x2.x;  sx[64 + c * 4 + 1] = x2.y;
        sx[64 + c * 4 + 2] = x2.z;  sx[64 + c * 4 + 3] = x2.w;
    }
    __syncwarp();
    const float2* sx2 = (const float2*)sX[threadIdx.y];
    float s = sb[lane];
#pragma unroll
    for (int j2 = 0; j2 < 48; j2++) {
        float2 x = sx2[j2];
        float2 w = __half22float2(sW2[j2 * 32 + lane]);
        s += x.x * w.x + x.y * w.y;
    }
    s = leaky(s, 0.01f);
    out[(size_t)v * ND + lane] = s;
    Tout[(size_t)v * ND + lane] = __float2half(s * dv);
}

// Layer-2 specialization: same as k_chebBL but h never hits gmem — the epilogue
// computes fs_h = half(h@Ws+bs), fd_h = half(h@Wd+bd) directly.
__global__ void k_chebBL2(const int* __restrict__ rs, const int* __restrict__ csr_src,
                          const uint2* __restrict__ Tin, const uint2* __restrict__ X1h,
                          const float4* __restrict__ f, const int* __restrict__ deg,
                          const float* __restrict__ lam, const float* __restrict__ W,
                          const float* __restrict__ b,
                          const float* __restrict__ Wsrc, const float* __restrict__ bsrc,
                          const float* __restrict__ Wdst, const float* __restrict__ bdst,
                          __half* __restrict__ fsh, __half* __restrict__ fdh, int n) {
    __shared__ __half2 sW2[48 * 32];
    __shared__ __half2 sWs2[16 * 32], sWd2[16 * 32];
    __shared__ float sb[32], sbs[32], sbd[32];
    __shared__ float sX[8][96];
    __shared__ float sH[8][32];
    int t = threadIdx.y * 32 + threadIdx.x;
    for (int i = t; i < 48 * 32; i += 256) {
        int j2 = i >> 5, col = i & 31;
        sW2[i] = __floats2half2_rn(W[(2 * j2) * 32 + col], W[(2 * j2 + 1) * 32 + col]);
    }
    for (int i = t; i < 16 * 32; i += 256) {
        int j2 = i >> 5, col = i & 31;
        sWs2[i] = __floats2half2_rn(Wsrc[(2 * j2) * 32 + col], Wsrc[(2 * j2 + 1) * 32 + col]);
        sWd2[i] = __floats2half2_rn(Wdst[(2 * j2) * 32 + col], Wdst[(2 * j2 + 1) * 32 + col]);
    }
    if (t < 32) { sb[t] = b[t]; sbs[t] = bsrc[t]; sbd[t] = bdst[t]; }
    __syncthreads();

    int v = blockIdx.x * 8 + threadIdx.y;
    if (v >= n) return;
    int lane = threadIdx.x;
    int g = lane >> 3, c = lane & 7;
    int beg = rs[v], end = rs[v + 1];
    float4 acc = row_sum4h(beg, end, csr_src, Tin, g, c);
    float dv = rsqrtf(fmaxf((float)__ldg(deg + v), 1.0f));
    if (g == 0) {
        float r = 2.0f / lam[0];
        float4 x1 = h4_to_f4(__ldg(X1h + (size_t)v * 8 + c));
        float4 f4 = __ldg(f + (size_t)v * 8 + c);
        float4 x2;
        x2.x = -2.0f * r * acc.x * dv + 2.0f * (r - 1.0f) * x1.x - f4.x;
        x2.y = -2.0f * r * acc.y * dv + 2.0f * (r - 1.0f) * x1.y - f4.y;
        x2.z = -2.0f * r * acc.z * dv + 2.0f * (r - 1.0f) * x1.z - f4.z;
        x2.w = -2.0f * r * acc.w * dv + 2.0f * (r - 1.0f) * x1.w - f4.w;
        float* sx = sX[threadIdx.y];
        sx[c * 4 + 0] = f4.x;  sx[c * 4 + 1] = f4.y;
        sx[c * 4 + 2] = f4.z;  sx[c * 4 + 3] = f4.w;
        sx[32 + c * 4 + 0] = x1.x;  sx[32 + c * 4 + 1] = x1.y;
        sx[32 + c * 4 + 2] = x1.z;  sx[32 + c * 4 + 3] = x1.w;
        sx[64 + c * 4 + 0] = x2.x;  sx[64 + c * 4 + 1] = x2.y;
        sx[64 + c * 4 + 2] = x2.z;  sx[64 + c * 4 + 3] = x2.w;
    }
    __syncwarp();
    const float2* sx2 = (const float2*)sX[threadIdx.y];
    float s = sb[lane];
#pragma unroll
    for (int j2 = 0; j2 < 48; j2++) {
        float2 x = sx2[j2];
        float2 w = __half22float2(sW2[j2 * 32 + lane]);
        s += x.x * w.x + x.y * w.y;
    }
    s = leaky(s, 0.01f);
    sH[threadIdx.y][lane] = s;
    __syncwarp();
    const float2* sh2 = (const float2*)sH[threadIdx.y];
    float a = sbs[lane], d = sbd[lane];
#pragma unroll
    for (int j2 = 0; j2 < 16; j2++) {
        float2 x = sh2[j2];
        float2 ws = __half22float2(sWs2[j2 * 32 + lane]);
        float2 wd = __half22float2(sWd2[j2 * 32 + lane]);
        a += x.x * ws.x + x.y * ws.y;
        d += x.x * wd.x + x.y * wd.y;
    }
    fsh[(size_t)v * ND + lane] = __float2half(a);
    fdh[(size_t)v * ND + lane] = __float2half(d);
}

// ---------------------------------------------------------------------------
// fused GATv2: one CSR pass, plain softmax (shift-invariant; logits O(10)),
// 4 edges x 8 lanes per warp, fs/fd rows fp16. Re-zeros deg for next run.
// ---------------------------------------------------------------------------
__device__ __forceinline__ float edge_logit(float4 f0, float4 fd4, float4 w) {
    float t = leaky(f0.x + fd4.x, 0.2f) * w.x + leaky(f0.y + fd4.y, 0.2f) * w.y +
              leaky(f0.z + fd4.z, 0.2f) * w.z + leaky(f0.w + fd4.w, 0.2f) * w.w;
    t += __shfl_xor_sync(0xffffffffu, t, 1);
    t += __shfl_xor_sync(0xffffffffu, t, 2);
    t += __shfl_xor_sync(0xffffffffu, t, 4);
    return t;
}

__global__ void k_gat(const int* __restrict__ rs, const int* __restrict__ csr_src,
                      const uint2* __restrict__ fsh, const uint2* __restrict__ fdh,
                      const float4* __restrict__ attn, float4* __restrict__ out,
                      int* __restrict__ deg, int n) {
    int v = blockIdx.x * 8 + threadIdx.y;
    if (v >= n) return;
    int lane = threadIdx.x;
    int g = lane >> 3, c = lane & 7;
    int beg = rs[v], end = rs[v + 1];
    float4 fd4 = h4_to_f4(__ldg(fdh + (size_t)v * 8 + c));
    float4 w = __ldg(attn + c);
    float den = 0.0f;
    float4 acc = make_float4(0.f, 0.f, 0.f, 0.f);
    int base = beg;
    for (; base + 8 <= end; base += 8) {
        int s0 = __ldg(csr_src + base + g);
        int s1 = __ldg(csr_src + base + 4 + g);
        float4 f0 = h4_to_f4(__ldg(fsh + (size_t)s0 * 8 + c));
        float4 f1 = h4_to_f4(__ldg(fsh + (size_t)s1 * 8 + c));
        float t0 = edge_logit(f0, fd4, w);
        float t1 = edge_logit(f1, fd4, w);
        float e0 = __expf(t0);
        float e1 = __expf(t1);
        den += e0 + e1;
        acc.x += f0.x * e0 + f1.x * e1;
        acc.y += f0.y * e0 + f1.y * e1;
        acc.z += f0.z * e0 + f1.z * e1;
        acc.w += f0.w * e0 + f1.w * e1;
    }
    for (; base < end; base += 4) {
        int p = base + g;
        bool valid = p < end;
        int s0 = valid ? __ldg(csr_src + p) : 0;
        float4 f0 = h4_to_f4(__ldg(fsh + (size_t)s0 * 8 + c));
        float t0 = edge_logit(f0, fd4, w);  // all lanes participate in shfl
        if (valid) {
            float e0 = __expf(t0);
            den += e0;
            acc.x += f0.x * e0;
            acc.y += f0.y * e0;
            acc.z += f0.z * e0;
            acc.w += f0.w * e0;
        }
    }
#pragma unroll
    for (int o = 8; o <= 16; o <<= 1) {
        den   += __shfl_xor_sync(0xffffffffu, den,   o);
        acc.x += __shfl_xor_sync(0xffffffffu, acc.x, o);
        acc.y += __shfl_xor_sync(0xffffffffu, acc.y, o);
        acc.z += __shfl_xor_sync(0xffffffffu, acc.z, o);
        acc.w += __shfl_xor_sync(0xffffffffu, acc.w, o);
    }
    if (g == 0) {
        float inv = (den > 0.0f) ? 1.0f / den : 0.0f;
        float4 o;
        o.x = leaky(acc.x * inv, 0.01f);
        o.y = leaky(acc.y * inv, 0.01f);
        o.z = leaky(acc.z * inv, 0.01f);
        o.w = leaky(acc.w * inv, 0.01f);
        out[(size_t)v * 8 + c] = o;
        if (c == 0) deg[v] = 0;  // ready for next run / replay
    }
}

// ---------------------------------------------------------------------------
// launch
// ---------------------------------------------------------------------------
extern "C" void kernel_launch(void* const* d_in, const int* in_sizes, int n_in,
                              void* d_out, int out_size) {
    const int*   src  = (const int*)d_in[0];
    const int*   dst  = (const int*)d_in[1];
    const float* emb  = (const float*)d_in[2];
    const float* lam  = (const float*)d_in[3];
    const float* chW  = (const float*)d_in[4];
    const float* chb  = (const float*)d_in[5];
    const float* Ws   = (const float*)d_in[6];
    const float* bs   = (const float*)d_in[7];
    const float* Wd   = (const float*)d_in[8];
    const float* bd   = (const float*)d_in[9];
    const float* attn = (const float*)d_in[10];

    const int E = in_sizes[0];
    const int n = in_sizes[2] / ND;

    float* base = nullptr;
    cudaGetSymbolAddress((void**)&base, g_buf);

    float*  h1      = base;
    __half* T0h     = (__half*)(base + 1 * SLOT);
    __half* T1h     = (__half*)(base + 1 * SLOT + SLOT / 2);
    __half* X1h     = (__half*)(base + 2 * SLOT);
    __half* fsh     = (__half*)(base + 2 * SLOT + SLOT / 2);
    __half* fdh     = (__half*)(base + 3 * SLOT);
    int*    csr_src = (int*)(base + 4 * SLOT);
    float*  tail    = base + 4 * SLOT + MAXE;
    int*    deg     = (int*)tail;
    int*    rs      = (int*)(tail + MAXN);          // N+1
    int*    cursor  = (int*)(tail + 2 * MAXN + 64);
    int*    blk     = (int*)(tail + 3 * MAXN + 64);

    const int nt = 256;
    auto g = [&](long x) { return (int)((x + nt - 1) / nt); };
    const int gV4   = g((long)n * 8);
    const int gEdge = g((long)E);
    const int gNW   = (n + 7) / 8;
    dim3 bNW(32, 8);
    const int nb = (n + 1023) / 1024;

    // --- CSR build (deg already zero: static init / re-zeroed by k_gat) ---
    k_deg<<<gEdge, nt>>>(dst, deg, E);
    k_scan1<<<nb, 1024>>>(deg, rs, blk, n);
    k_scan2<<<1, 128>>>(blk, nb);
    k_scan3p<<<gV4, nt>>>(rs, cursor, blk, deg, (const float4*)emb, (uint2*)T0h, n, E);
    k_fill<<<gEdge, nt>>>(src, dst, cursor, csr_src, E);

    // --- ChebConv 1 (input = embedding) ---
    k_chebA<<<gNW, bNW>>>(rs, csr_src, (const uint2*)T0h, (const float4*)emb,
                          deg, lam, (uint2*)X1h, (uint2*)T1h, n);
    k_chebBL<<<gNW, bNW>>>(rs, csr_src, (const uint2*)T1h, (const uint2*)X1h,
                           (const float4*)emb, deg, lam, chW, chb, h1, T0h, n);

    // --- ChebConv 2 (input = h1; T0h = h1*dinv) + fused GAT projections ---
    k_chebA<<<gNW, bNW>>>(rs, csr_src, (const uint2*)T0h, (const float4*)h1,
                          deg, lam, (uint2*)X1h, (uint2*)T1h, n);
    k_chebBL2<<<gNW, bNW>>>(rs, csr_src, (const uint2*)T1h, (const uint2*)X1h,
                            (const float4*)h1, deg, lam, chW, chb,
                            Ws, bs, Wd, bd, fsh, fdh, n);

    // --- GATv2 (fused single pass, fp16 fs/fd, plain softmax) ---
    k_gat<<<gNW, bNW>>>(rs, csr_src, (const uint2*)fsh, (const uint2*)fdh,
                        (const float4*)attn, (float4*)d_out, deg, n);
}

// round 16
// speedup vs baseline: 1.4420x; 1.0696x over previous
#include <cuda_runtime.h>
#include <cuda_fp16.h>

#define ND 32
#define MAXN 100000
#define MAXE 1600000

static constexpr size_t SLOT = (size_t)MAXN * ND;

// Scratch arena (floats):
//  h1 : SLOT fp32
//  T0h,T1h,X1h,fsh,fdh : 5 * SLOT/2 (fp16 rows)
//  csr_src : MAXE int
//  tail: deg(N), rs(N+1), cursor(N), blk(128), wbuf(2560 half2)
__device__ __align__(256) float g_buf[4 * SLOT + (size_t)MAXE + 6 * (size_t)MAXN + 4096];

__device__ __forceinline__ float leaky(float x, float s) {
    return x > 0.0f ? x : s * x;
}
__device__ __forceinline__ uint2 f4_to_h4(float4 v) {
    __half2 a = __floats2half2_rn(v.x, v.y);
    __half2 b = __floats2half2_rn(v.z, v.w);
    uint2 r;
    r.x = *(unsigned*)&a;
    r.y = *(unsigned*)&b;
    return r;
}
__device__ __forceinline__ float4 h4_to_f4(uint2 u) {
    __half2 a = *(__half2*)&u.x;
    __half2 b = *(__half2*)&u.y;
    float2 fa = __half22float2(a), fb = __half22float2(b);
    return make_float4(fa.x, fa.y, fb.x, fb.y);
}

// ---------------------------------------------------------------------------
// degree + scan + CSR fill  (deg zeroed by k_gat at end of previous run;
// static zero-init covers the first call)
// ---------------------------------------------------------------------------
__global__ void k_deg(const int* __restrict__ dst, int* __restrict__ deg, int E) {
    int e = blockIdx.x * blockDim.x + threadIdx.x;
    if (e < E) atomicAdd(&deg[dst[e]], 1);
}

__global__ void k_scan1(const int* __restrict__ deg, int* __restrict__ rs,
                        int* __restrict__ blk, int n) {
    __shared__ int sh[1024];
    int i = blockIdx.x * 1024 + threadIdx.x;
    int v = (i < n) ? deg[i] : 0;
    sh[threadIdx.x] = v;
    __syncthreads();
#pragma unroll
    for (int o = 1; o < 1024; o <<= 1) {
        int t = (threadIdx.x >= o) ? sh[threadIdx.x - o] : 0;
        __syncthreads();
        sh[threadIdx.x] += t;
        __syncthreads();
    }
    if (i < n) rs[i] = sh[threadIdx.x] - v;
    if (threadIdx.x == 1023) blk[blockIdx.x] = sh[1023];
}

__global__ void k_scan2(int* __restrict__ blk, int nb) {
    __shared__ int sh[128];
    int t = threadIdx.x;
    int v = (t < nb) ? blk[t] : 0;
    sh[t] = v;
    __syncthreads();
#pragma unroll
    for (int o = 1; o < 128; o <<= 1) {
        int x = (t >= o) ? sh[t - o] : 0;
        __syncthreads();
        sh[t] += x;
        __syncthreads();
    }
    if (t < nb) blk[t] = sh[t] - v;
}

// finalize row starts + cursors; also T0h = half(emb * dinv)  (fused prescale)
__global__ void k_scan3p(int* __restrict__ rs, int* __restrict__ cursor,
                         const int* __restrict__ blk, const int* __restrict__ deg,
                         const float4* __restrict__ emb, uint2* __restrict__ T0h,
                         int n, int E) {
    int i = blockIdx.x * blockDim.x + threadIdx.x;
    if (i >= n * 8) return;
    int node = i >> 3;
    float dv = rsqrtf(fmaxf((float)__ldg(deg + node), 1.0f));
    float4 v = __ldg(emb + i);
    v.x *= dv; v.y *= dv; v.z *= dv; v.w *= dv;
    T0h[i] = f4_to_h4(v);
    if ((i & 7) == 0) {
        int p = rs[node] + blk[node >> 10];
        rs[node] = p;
        cursor[node] = p;
        if (node == 0) rs[n] = E;
    }
}

__global__ void k_fill(const int* __restrict__ src, const int* __restrict__ dst,
                       int* __restrict__ cursor, int* __restrict__ csr_src, int E) {
    int e = blockIdx.x * blockDim.x + threadIdx.x;
    if (e >= E) return;
    int p = atomicAdd(&cursor[dst[e]], 1);
    csr_src[p] = src[e];
}

// ---------------------------------------------------------------------------
// one-shot weight conversion: wc layout (half2, pair-major):
//   [0, 48*32)        : chW pairs   wc[j2*32+col] = (W[2j2][col], W[2j2+1][col])
//   [48*32, 64*32)    : Ws pairs (16 j2)
//   [64*32, 80*32)    : Wd pairs (16 j2)
// ---------------------------------------------------------------------------
__global__ void k_wconv(const float* __restrict__ W, const float* __restrict__ Ws,
                        const float* __restrict__ Wd, __half2* __restrict__ wc) {
    int i = blockIdx.x * blockDim.x + threadIdx.x;
    if (i < 48 * 32) {
        int j2 = i >> 5, col = i & 31;
        wc[i] = __floats2half2_rn(W[(2 * j2) * 32 + col], W[(2 * j2 + 1) * 32 + col]);
    } else if (i < 64 * 32) {
        int k = i - 48 * 32;
        int j2 = k >> 5, col = k & 31;
        wc[i] = __floats2half2_rn(Ws[(2 * j2) * 32 + col], Ws[(2 * j2 + 1) * 32 + col]);
    } else if (i < 80 * 32) {
        int k = i - 64 * 32;
        int j2 = k >> 5, col = k & 31;
        wc[i] = __floats2half2_rn(Wd[(2 * j2) * 32 + col], Wd[(2 * j2 + 1) * 32 + col]);
    }
}

// ---------------------------------------------------------------------------
// warp-per-node CSR row sum over fp16 rows: 4 edges x 8 lanes (uint2/lane),
// up to 4 rows in flight per group. fp32 accum.
// ---------------------------------------------------------------------------
__device__ __forceinline__ float4 row_sum4h(int beg, int end,
                                            const int* __restrict__ csr_src,
                                            const uint2* __restrict__ Th,
                                            int g, int c) {
    float4 acc = make_float4(0.f, 0.f, 0.f, 0.f);
    int base = beg;
    for (; base + 16 <= end; base += 16) {
        int i0 = __ldg(csr_src + base + g);
        int i1 = __ldg(csr_src + base + 4 + g);
        int i2 = __ldg(csr_src + base + 8 + g);
        int i3 = __ldg(csr_src + base + 12 + g);
        float4 v0 = h4_to_f4(__ldg(Th + (size_t)i0 * 8 + c));
        float4 v1 = h4_to_f4(__ldg(Th + (size_t)i1 * 8 + c));
        float4 v2 = h4_to_f4(__ldg(Th + (size_t)i2 * 8 + c));
        float4 v3 = h4_to_f4(__ldg(Th + (size_t)i3 * 8 + c));
        acc.x += (v0.x + v1.x) + (v2.x + v3.x);
        acc.y += (v0.y + v1.y) + (v2.y + v3.y);
        acc.z += (v0.z + v1.z) + (v2.z + v3.z);
        acc.w += (v0.w + v1.w) + (v2.w + v3.w);
    }
    for (; base + 8 <= end; base += 8) {
        int i0 = __ldg(csr_src + base + g);
        int i1 = __ldg(csr_src + base + 4 + g);
        float4 v0 = h4_to_f4(__ldg(Th + (size_t)i0 * 8 + c));
        float4 v1 = h4_to_f4(__ldg(Th + (size_t)i1 * 8 + c));
        acc.x += v0.x + v1.x;
        acc.y += v0.y + v1.y;
        acc.z += v0.z + v1.z;
        acc.w += v0.w + v1.w;
    }
    for (; base < end; base += 4) {
        int p = base + g;
        if (p < end) {
            int i0 = __ldg(csr_src + p);
            float4 v0 = h4_to_f4(__ldg(Th + (size_t)i0 * 8 + c));
            acc.x += v0.x; acc.y += v0.y; acc.z += v0.z; acc.w += v0.w;
        }
    }
#pragma unroll
    for (int o = 8; o <= 16; o <<= 1) {
        acc.x += __shfl_xor_sync(0xffffffffu, acc.x, o);
        acc.y += __shfl_xor_sync(0xffffffffu, acc.y, o);
        acc.z += __shfl_xor_sync(0xffffffffu, acc.z, o);
        acc.w += __shfl_xor_sync(0xffffffffu, acc.w, o);
    }
    return acc;
}

// X1h = half(-r*acc*dv + (r-1)*f); T1h = half(X1*dv)
__global__ void k_chebA(const int* __restrict__ rs, const int* __restrict__ csr_src,
                        const uint2* __restrict__ Tin, const float4* __restrict__ f,
                        const int* __restrict__ deg, const float* __restrict__ lam,
                        uint2* __restrict__ X1h, uint2* __restrict__ Tout, int n) {
    int v = blockIdx.x * 8 + threadIdx.y;
    if (v >= n) return;
    int lane = threadIdx.x;
    int g = lane >> 3, c = lane & 7;
    int beg = rs[v], end = rs[v + 1];
    float4 acc = row_sum4h(beg, end, csr_src, Tin, g, c);
    if (g == 0) {
        float r = 2.0f / lam[0];
        float dv = rsqrtf(fmaxf((float)__ldg(deg + v), 1.0f));
        float4 f4 = __ldg(f + (size_t)v * 8 + c);
        float4 x1;
        x1.x = -r * acc.x * dv + (r - 1.0f) * f4.x;
        x1.y = -r * acc.y * dv + (r - 1.0f) * f4.y;
        x1.z = -r * acc.z * dv + (r - 1.0f) * f4.z;
        x1.w = -r * acc.w * dv + (r - 1.0f) * f4.w;
        X1h[(size_t)v * 8 + c] = f4_to_h4(x1);
        float4 t;
        t.x = x1.x * dv; t.y = x1.y * dv; t.z = x1.z * dv; t.w = x1.w * dv;
        Tout[(size_t)v * 8 + c] = f4_to_h4(t);
    }
}

// Fused: acc = L-gather(T1h); X2 = -2r*acc*dv + 2(r-1)*X1 - f;
// out = leaky([X0,X1,X2] @ W + b); Tout_h = half(out*dinv)
// Weights read directly (pre-converted half2, L1-resident). No block staging.
__global__ void k_chebBL(const int* __restrict__ rs, const int* __restrict__ csr_src,
                         const uint2* __restrict__ Tin, const uint2* __restrict__ X1h,
                         const float4* __restrict__ f, const int* __restrict__ deg,
                         const float* __restrict__ lam, const __half2* __restrict__ Wc,
                         const float* __restrict__ b, float* __restrict__ out,
                         __half* __restrict__ Tout, int n) {
    __shared__ float sX[8][96];
    int v = blockIdx.x * 8 + threadIdx.y;
    if (v >= n) return;
    int lane = threadIdx.x;
    int g = lane >> 3, c = lane & 7;
    int beg = rs[v], end = rs[v + 1];
    float4 acc = row_sum4h(beg, end, csr_src, Tin, g, c);
    float dv = rsqrtf(fmaxf((float)__ldg(deg + v), 1.0f));
    if (g == 0) {
        float r = 2.0f / lam[0];
        float4 x1 = h4_to_f4(__ldg(X1h + (size_t)v * 8 + c));
        float4 f4 = __ldg(f + (size_t)v * 8 + c);
        float4 x2;
        x2.x = -2.0f * r * acc.x * dv + 2.0f * (r - 1.0f) * x1.x - f4.x;
        x2.y = -2.0f * r * acc.y * dv + 2.0f * (r - 1.0f) * x1.y - f4.y;
        x2.z = -2.0f * r * acc.z * dv + 2.0f * (r - 1.0f) * x1.z - f4.z;
        x2.w = -2.0f * r * acc.w * dv + 2.0f * (r - 1.0f) * x1.w - f4.w;
        float* sx = sX[threadIdx.y];
        sx[c * 4 + 0] = f4.x;  sx[c * 4 + 1] = f4.y;
        sx[c * 4 + 2] = f4.z;  sx[c * 4 + 3] = f4.w;
        sx[32 + c * 4 + 0] = x1.x;  sx[32 + c * 4 + 1] = x1.y;
        sx[32 + c * 4 + 2] = x1.z;  sx[32 + c * 4 + 3] = x1.w;
        sx[64 + c * 4 + 0] = x2.x;  sx[64 + c * 4 + 1] = x2.y;
        sx[64 + c * 4 + 2] = x2.z;  sx[64 + c * 4 + 3] = x2.w;
    }
    __syncwarp();
    const float2* sx2 = (const float2*)sX[threadIdx.y];
    float s = __ldg(b + lane);
#pragma unroll
    for (int j2 = 0; j2 < 48; j2++) {
        float2 x = sx2[j2];
        float2 w = __half22float2(__ldg(Wc + j2 * 32 + lane));
        s += x.x * w.x + x.y * w.y;
    }
    s = leaky(s, 0.01f);
    out[(size_t)v * ND + lane] = s;
    Tout[(size_t)v * ND + lane] = __float2half(s * dv);
}

// Layer-2 specialization: h never hits gmem — epilogue computes
// fs_h = half(h@Ws+bs), fd_h = half(h@Wd+bd) directly. Weights via L1.
__global__ void k_chebBL2(const int* __restrict__ rs, const int* __restrict__ csr_src,
                          const uint2* __restrict__ Tin, const uint2* __restrict__ X1h,
                          const float4* __restrict__ f, const int* __restrict__ deg,
                          const float* __restrict__ lam, const __half2* __restrict__ Wc,
                          const float* __restrict__ b,
                          const float* __restrict__ bsrc, const float* __restrict__ bdst,
                          __half* __restrict__ fsh, __half* __restrict__ fdh, int n) {
    __shared__ float sX[8][96];
    __shared__ float sH[8][32];
    int v = blockIdx.x * 8 + threadIdx.y;
    if (v >= n) return;
    int lane = threadIdx.x;
    int g = lane >> 3, c = lane & 7;
    int beg = rs[v], end = rs[v + 1];
    float4 acc = row_sum4h(beg, end, csr_src, Tin, g, c);
    float dv = rsqrtf(fmaxf((float)__ldg(deg + v), 1.0f));
    if (g == 0) {
        float r = 2.0f / lam[0];
        float4 x1 = h4_to_f4(__ldg(X1h + (size_t)v * 8 + c));
        float4 f4 = __ldg(f + (size_t)v * 8 + c);
        float4 x2;
        x2.x = -2.0f * r * acc.x * dv + 2.0f * (r - 1.0f) * x1.x - f4.x;
        x2.y = -2.0f * r * acc.y * dv + 2.0f * (r - 1.0f) * x1.y - f4.y;
        x2.z = -2.0f * r * acc.z * dv + 2.0f * (r - 1.0f) * x1.z - f4.z;
        x2.w = -2.0f * r * acc.w * dv + 2.0f * (r - 1.0f) * x1.w - f4.w;
        float* sx = sX[threadIdx.y];
        sx[c * 4 + 0] = f4.x;  sx[c * 4 + 1] = f4.y;
        sx[c * 4 + 2] = f4.z;  sx[c * 4 + 3] = f4.w;
        sx[32 + c * 4 + 0] = x1.x;  sx[32 + c * 4 + 1] = x1.y;
        sx[32 + c * 4 + 2] = x1.z;  sx[32 + c * 4 + 3] = x1.w;
        sx[64 + c * 4 + 0] = x2.x;  sx[64 + c * 4 + 1] = x2.y;
        sx[64 + c * 4 + 2] = x2.z;  sx[64 + c * 4 + 3] = x2.w;
    }
    __syncwarp();
    const float2* sx2 = (const float2*)sX[threadIdx.y];
    float s = __ldg(b + lane);
#pragma unroll
    for (int j2 = 0; j2 < 48; j2++) {
        float2 x = sx2[j2];
        float2 w = __half22float2(__ldg(Wc + j2 * 32 + lane));
        s += x.x * w.x + x.y * w.y;
    }
    s = leaky(s, 0.01f);
    sH[threadIdx.y][lane] = s;
    __syncwarp();
    const float2* sh2 = (const float2*)sH[threadIdx.y];
    float a = __ldg(bsrc + lane), d = __ldg(bdst + lane);
    const __half2* Ws2 = Wc + 48 * 32;
    const __half2* Wd2 = Wc + 64 * 32;
#pragma unroll
    for (int j2 = 0; j2 < 16; j2++) {
        float2 x = sh2[j2];
        float2 ws = __half22float2(__ldg(Ws2 + j2 * 32 + lane));
        float2 wd = __half22float2(__ldg(Wd2 + j2 * 32 + lane));
        a += x.x * ws.x + x.y * ws.y;
        d += x.x * wd.x + x.y * wd.y;
    }
    fsh[(size_t)v * ND + lane] = __float2half(a);
    fdh[(size_t)v * ND + lane] = __float2half(d);
}

// ---------------------------------------------------------------------------
// fused GATv2: one CSR pass, plain softmax (shift-invariant; logits O(10)),
// 4 edges x 8 lanes per warp, fs/fd rows fp16. Re-zeros deg for next run.
// ---------------------------------------------------------------------------
__device__ __forceinline__ float edge_logit(float4 f0, float4 fd4, float4 w) {
    float t = leaky(f0.x + fd4.x, 0.2f) * w.x + leaky(f0.y + fd4.y, 0.2f) * w.y +
              leaky(f0.z + fd4.z, 0.2f) * w.z + leaky(f0.w + fd4.w, 0.2f) * w.w;
    t += __shfl_xor_sync(0xffffffffu, t, 1);
    t += __shfl_xor_sync(0xffffffffu, t, 2);
    t += __shfl_xor_sync(0xffffffffu, t, 4);
    return t;
}

__global__ void k_gat(const int* __restrict__ rs, const int* __restrict__ csr_src,
                      const uint2* __restrict__ fsh, const uint2* __restrict__ fdh,
                      const float4* __restrict__ attn, float4* __restrict__ out,
                      int* __restrict__ deg, int n) {
    int v = blockIdx.x * 8 + threadIdx.y;
    if (v >= n) return;
    int lane = threadIdx.x;
    int g = lane >> 3, c = lane & 7;
    int beg = rs[v], end = rs[v + 1];
    float4 fd4 = h4_to_f4(__ldg(fdh + (size_t)v * 8 + c));
    float4 w = __ldg(attn + c);
    float den = 0.0f;
    float4 acc = make_float4(0.f, 0.f, 0.f, 0.f);
    int base = beg;
    for (; base + 8 <= end; base += 8) {
        int s0 = __ldg(csr_src + base + g);
        int s1 = __ldg(csr_src + base + 4 + g);
        float4 f0 = h4_to_f4(__ldg(fsh + (size_t)s0 * 8 + c));
        float4 f1 = h4_to_f4(__ldg(fsh + (size_t)s1 * 8 + c));
        float t0 = edge_logit(f0, fd4, w);
        float t1 = edge_logit(f1, fd4, w);
        float e0 = __expf(t0);
        float e1 = __expf(t1);
        den += e0 + e1;
        acc.x += f0.x * e0 + f1.x * e1;
        acc.y += f0.y * e0 + f1.y * e1;
        acc.z += f0.z * e0 + f1.z * e1;
        acc.w += f0.w * e0 + f1.w * e1;
    }
    for (; base < end; base += 4) {
        int p = base + g;
        bool valid = p < end;
        int s0 = valid ? __ldg(csr_src + p) : 0;
        float4 f0 = h4_to_f4(__ldg(fsh + (size_t)s0 * 8 + c));
        float t0 = edge_logit(f0, fd4, w);  // all lanes participate in shfl
        if (valid) {
            float e0 = __expf(t0);
            den += e0;
            acc.x += f0.x * e0;
            acc.y += f0.y * e0;
            acc.z += f0.z * e0;
            acc.w += f0.w * e0;
        }
    }
#pragma unroll
    for (int o = 8; o <= 16; o <<= 1) {
        den   += __shfl_xor_sync(0xffffffffu, den,   o);
        acc.x += __shfl_xor_sync(0xffffffffu, acc.x, o);
        acc.y += __shfl_xor_sync(0xffffffffu, acc.y, o);
        acc.z += __shfl_xor_sync(0xffffffffu, acc.z, o);
        acc.w += __shfl_xor_sync(0xffffffffu, acc.w, o);
    }
    if (g == 0) {
        float inv = (den > 0.0f) ? 1.0f / den : 0.0f;
        float4 o;
        o.x = leaky(acc.x * inv, 0.01f);
        o.y = leaky(acc.y * inv, 0.01f);
        o.z = leaky(acc.z * inv, 0.01f);
        o.w = leaky(acc.w * inv, 0.01f);
        out[(size_t)v * 8 + c] = o;
        if (c == 0) deg[v] = 0;  // ready for next run / replay
    }
}

// ---------------------------------------------------------------------------
// launch
// ---------------------------------------------------------------------------
extern "C" void kernel_launch(void* const* d_in, const int* in_sizes, int n_in,
                              void* d_out, int out_size) {
    const int*   src  = (const int*)d_in[0];
    const int*   dst  = (const int*)d_in[1];
    const float* emb  = (const float*)d_in[2];
    const float* lam  = (const float*)d_in[3];
    const float* chW  = (const float*)d_in[4];
    const float* chb  = (const float*)d_in[5];
    const float* Ws   = (const float*)d_in[6];
    const float* bs   = (const float*)d_in[7];
    const float* Wd   = (const float*)d_in[8];
    const float* bd   = (const float*)d_in[9];
    const float* attn = (const float*)d_in[10];

    const int E = in_sizes[0];
    const int n = in_sizes[2] / ND;

    float* base = nullptr;
    cudaGetSymbolAddress((void**)&base, g_buf);

    float*  h1      = base;
    __half* T0h     = (__half*)(base + 1 * SLOT);
    __half* T1h     = (__half*)(base + 1 * SLOT + SLOT / 2);
    __half* X1h     = (__half*)(base + 2 * SLOT);
    __half* fsh     = (__half*)(base + 2 * SLOT + SLOT / 2);
    __half* fdh     = (__half*)(base + 3 * SLOT);
    int*    csr_src = (int*)(base + 4 * SLOT);
    float*  tail    = base + 4 * SLOT + MAXE;
    int*    deg     = (int*)tail;
    int*    rs      = (int*)(tail + MAXN);          // N+1
    int*    cursor  = (int*)(tail + 2 * MAXN + 64);
    int*    blk     = (int*)(tail + 3 * MAXN + 64);
    __half2* wc     = (__half2*)(tail + 3 * MAXN + 256);  // 2560 half2 = 2560 floats

    const int nt = 256;
    auto g = [&](long x) { return (int)((x + nt - 1) / nt); };
    const int gV4   = g((long)n * 8);
    const int gEdge = g((long)E);
    const int gNW   = (n + 7) / 8;
    dim3 bNW(32, 8);
    const int nb = (n + 1023) / 1024;

    // --- weight pre-conversion (20 KB, one-shot) ---
    k_wconv<<<10, 256>>>(chW, Ws, Wd, wc);

    // --- CSR build (deg already zero: static init / re-zeroed by k_gat) ---
    k_deg<<<gEdge, nt>>>(dst, deg, E);
    k_scan1<<<nb, 1024>>>(deg, rs, blk, n);
    k_scan2<<<1, 128>>>(blk, nb);
    k_scan3p<<<gV4, nt>>>(rs, cursor, blk, deg, (const float4*)emb, (uint2*)T0h, n, E);
    k_fill<<<gEdge, nt>>>(src, dst, cursor, csr_src, E);

    // --- ChebConv 1 (input = embedding) ---
    k_chebA<<<gNW, bNW>>>(rs, csr_src, (const uint2*)T0h, (const float4*)emb,
                          deg, lam, (uint2*)X1h, (uint2*)T1h, n);
    k_chebBL<<<gNW, bNW>>>(rs, csr_src, (const uint2*)T1h, (const uint2*)X1h,
                           (const float4*)emb, deg, lam, wc, chb, h1, T0h, n);

    // --- ChebConv 2 (input = h1; T0h = h1*dinv) + fused GAT projections ---
    k_chebA<<<gNW, bNW>>>(rs, csr_src, (const uint2*)T0h, (const float4*)h1,
                          deg, lam, (uint2*)X1h, (uint2*)T1h, n);
    k_chebBL2<<<gNW, bNW>>>(rs, csr_src, (const uint2*)T1h, (const uint2*)X1h,
                            (const float4*)h1, deg, lam, wc, chb,
                            bs, bd, fsh, fdh, n);

    // --- GATv2 (fused single pass, fp16 fs/fd, plain softmax) ---
    k_gat<<<gNW, bNW>>>(rs, csr_src, (const uint2*)fsh, (const uint2*)fdh,
                        (const float4*)attn, (float4*)d_out, deg, n);
}

// round 17
// speedup vs baseline: 1.4616x; 1.0136x over previous
#include <cuda_runtime.h>
#include <cuda_fp16.h>

#define ND 32
#define MAXN 100000
#define MAXE 1600000

static constexpr size_t SLOT = (size_t)MAXN * ND;

// Scratch arena (floats):
//  h1h,T0h,T1h,fsh,fdh : 5 * SLOT/2 (fp16 rows)
//  csr_src : MAXE int
//  tail: deg(N), rs(N+1), cursor(N), blk(128), wc(2560 half2)
__device__ __align__(256) float g_buf[3 * SLOT + (size_t)MAXE + 6 * (size_t)MAXN + 4096];

__device__ __forceinline__ float leaky(float x, float s) {
    return x > 0.0f ? x : s * x;
}
__device__ __forceinline__ uint2 f4_to_h4(float4 v) {
    __half2 a = __floats2half2_rn(v.x, v.y);
    __half2 b = __floats2half2_rn(v.z, v.w);
    uint2 r;
    r.x = *(unsigned*)&a;
    r.y = *(unsigned*)&b;
    return r;
}
__device__ __forceinline__ float4 h4_to_f4(uint2 u) {
    __half2 a = *(__half2*)&u.x;
    __half2 b = *(__half2*)&u.y;
    float2 fa = __half22float2(a), fb = __half22float2(b);
    return make_float4(fa.x, fa.y, fb.x, fb.y);
}

// ---------------------------------------------------------------------------
// degree (+ fused one-shot weight conversion in tail blocks)
// deg zeroed by k_gat at end of previous run; static zero-init covers call 1.
// wc layout (half2): [0,48*32) chW pairs | [48*32,64*32) Ws | [64*32,80*32) Wd
// ---------------------------------------------------------------------------
__global__ void k_deg(const int* __restrict__ dst, int* __restrict__ deg, int E,
                      int gEdge, const float* __restrict__ W,
                      const float* __restrict__ Ws, const float* __restrict__ Wd,
                      __half2* __restrict__ wc) {
    if ((int)blockIdx.x >= gEdge) {
        int i = (blockIdx.x - gEdge) * blockDim.x + threadIdx.x;
        if (i < 48 * 32) {
            int j2 = i >> 5, col = i & 31;
            wc[i] = __floats2half2_rn(W[(2 * j2) * 32 + col], W[(2 * j2 + 1) * 32 + col]);
        } else if (i < 64 * 32) {
            int k = i - 48 * 32;
            int j2 = k >> 5, col = k & 31;
            wc[i] = __floats2half2_rn(Ws[(2 * j2) * 32 + col], Ws[(2 * j2 + 1) * 32 + col]);
        } else if (i < 80 * 32) {
            int k = i - 64 * 32;
            int j2 = k >> 5, col = k & 31;
            wc[i] = __floats2half2_rn(Wd[(2 * j2) * 32 + col], Wd[(2 * j2 + 1) * 32 + col]);
        }
        return;
    }
    int e = blockIdx.x * blockDim.x + threadIdx.x;
    if (e < E) atomicAdd(&deg[dst[e]], 1);
}

__global__ void k_scan1(const int* __restrict__ deg, int* __restrict__ rs,
                        int* __restrict__ blk, int n) {
    __shared__ int sh[1024];
    int i = blockIdx.x * 1024 + threadIdx.x;
    int v = (i < n) ? deg[i] : 0;
    sh[threadIdx.x] = v;
    __syncthreads();
#pragma unroll
    for (int o = 1; o < 1024; o <<= 1) {
        int t = (threadIdx.x >= o) ? sh[threadIdx.x - o] : 0;
        __syncthreads();
        sh[threadIdx.x] += t;
        __syncthreads();
    }
    if (i < n) rs[i] = sh[threadIdx.x] - v;
    if (threadIdx.x == 1023) blk[blockIdx.x] = sh[1023];
}

__global__ void k_scan2(int* __restrict__ blk, int nb) {
    __shared__ int sh[128];
    int t = threadIdx.x;
    int v = (t < nb) ? blk[t] : 0;
    sh[t] = v;
    __syncthreads();
#pragma unroll
    for (int o = 1; o < 128; o <<= 1) {
        int x = (t >= o) ? sh[t - o] : 0;
        __syncthreads();
        sh[t] += x;
        __syncthreads();
    }
    if (t < nb) blk[t] = sh[t] - v;
}

// finalize row starts + cursors; also T0h = half(emb * dinv)  (fused prescale)
__global__ void k_scan3p(int* __restrict__ rs, int* __restrict__ cursor,
                         const int* __restrict__ blk, const int* __restrict__ deg,
                         const float4* __restrict__ emb, uint2* __restrict__ T0h,
                         int n, int E) {
    int i = blockIdx.x * blockDim.x + threadIdx.x;
    if (i >= n * 8) return;
    int node = i >> 3;
    float dv = rsqrtf(fmaxf((float)__ldg(deg + node), 1.0f));
    float4 v = __ldg(emb + i);
    v.x *= dv; v.y *= dv; v.z *= dv; v.w *= dv;
    T0h[i] = f4_to_h4(v);
    if ((i & 7) == 0) {
        int p = rs[node] + blk[node >> 10];
        rs[node] = p;
        cursor[node] = p;
        if (node == 0) rs[n] = E;
    }
}

__global__ void k_fill(const int* __restrict__ src, const int* __restrict__ dst,
                       int* __restrict__ cursor, int* __restrict__ csr_src, int E) {
    int e = blockIdx.x * blockDim.x + threadIdx.x;
    if (e >= E) return;
    int p = atomicAdd(&cursor[dst[e]], 1);
    csr_src[p] = src[e];
}

// ---------------------------------------------------------------------------
// warp-per-node CSR row sum over fp16 rows: 4 edges x 8 lanes (uint2/lane),
// up to 4 rows in flight per group. fp32 accum.
// ---------------------------------------------------------------------------
__device__ __forceinline__ float4 row_sum4h(int beg, int end,
                                            const int* __restrict__ csr_src,
                                            const uint2* __restrict__ Th,
                                            int g, int c) {
    float4 acc = make_float4(0.f, 0.f, 0.f, 0.f);
    int base = beg;
    for (; base + 16 <= end; base += 16) {
        int i0 = __ldg(csr_src + base + g);
        int i1 = __ldg(csr_src + base + 4 + g);
        int i2 = __ldg(csr_src + base + 8 + g);
        int i3 = __ldg(csr_src + base + 12 + g);
        float4 v0 = h4_to_f4(__ldg(Th + (size_t)i0 * 8 + c));
        float4 v1 = h4_to_f4(__ldg(Th + (size_t)i1 * 8 + c));
        float4 v2 = h4_to_f4(__ldg(Th + (size_t)i2 * 8 + c));
        float4 v3 = h4_to_f4(__ldg(Th + (size_t)i3 * 8 + c));
        acc.x += (v0.x + v1.x) + (v2.x + v3.x);
        acc.y += (v0.y + v1.y) + (v2.y + v3.y);
        acc.z += (v0.z + v1.z) + (v2.z + v3.z);
        acc.w += (v0.w + v1.w) + (v2.w + v3.w);
    }
    for (; base + 8 <= end; base += 8) {
        int i0 = __ldg(csr_src + base + g);
        int i1 = __ldg(csr_src + base + 4 + g);
        float4 v0 = h4_to_f4(__ldg(Th + (size_t)i0 * 8 + c));
        float4 v1 = h4_to_f4(__ldg(Th + (size_t)i1 * 8 + c));
        acc.x += v0.x + v1.x;
        acc.y += v0.y + v1.y;
        acc.z += v0.z + v1.z;
        acc.w += v0.w + v1.w;
    }
    for (; base < end; base += 4) {
        int p = base + g;
        if (p < end) {
            int i0 = __ldg(csr_src + p);
            float4 v0 = h4_to_f4(__ldg(Th + (size_t)i0 * 8 + c));
            acc.x += v0.x; acc.y += v0.y; acc.z += v0.z; acc.w += v0.w;
        }
    }
#pragma unroll
    for (int o = 8; o <= 16; o <<= 1) {
        acc.x += __shfl_xor_sync(0xffffffffu, acc.x, o);
        acc.y += __shfl_xor_sync(0xffffffffu, acc.y, o);
        acc.z += __shfl_xor_sync(0xffffffffu, acc.z, o);
        acc.w += __shfl_xor_sync(0xffffffffu, acc.w, o);
    }
    return acc;
}

// chebA layer1: f = emb fp32. T1h = half((-r*acc*dv + (r-1)*f) * dv). No X1 store.
__global__ void k_chebA1(const int* __restrict__ rs, const int* __restrict__ csr_src,
                         const uint2* __restrict__ Tin, const float4* __restrict__ f,
                         const int* __restrict__ deg, const float* __restrict__ lam,
                         uint2* __restrict__ Tout, int n) {
    int v = blockIdx.x * 8 + threadIdx.y;
    if (v >= n) return;
    int lane = threadIdx.x;
    int g = lane >> 3, c = lane & 7;
    int beg = rs[v], end = rs[v + 1];
    float4 acc = row_sum4h(beg, end, csr_src, Tin, g, c);
    if (g == 0) {
        float r = 2.0f / lam[0];
        float dv = rsqrtf(fmaxf((float)__ldg(deg + v), 1.0f));
        float4 f4 = __ldg(f + (size_t)v * 8 + c);
        float4 t;
        t.x = (-r * acc.x * dv + (r - 1.0f) * f4.x) * dv;
        t.y = (-r * acc.y * dv + (r - 1.0f) * f4.y) * dv;
        t.z = (-r * acc.z * dv + (r - 1.0f) * f4.z) * dv;
        t.w = (-r * acc.w * dv + (r - 1.0f) * f4.w) * dv;
        Tout[(size_t)v * 8 + c] = f4_to_h4(t);
    }
}

// chebA layer2: f = h1 fp16
__global__ void k_chebA2(const int* __restrict__ rs, const int* __restrict__ csr_src,
                         const uint2* __restrict__ Tin, const uint2* __restrict__ fh,
                         const int* __restrict__ deg, const float* __restrict__ lam,
                         uint2* __restrict__ Tout, int n) {
    int v = blockIdx.x * 8 + threadIdx.y;
    if (v >= n) return;
    int lane = threadIdx.x;
    int g = lane >> 3, c = lane & 7;
    int beg = rs[v], end = rs[v + 1];
    float4 acc = row_sum4h(beg, end, csr_src, Tin, g, c);
    if (g == 0) {
        float r = 2.0f / lam[0];
        float dv = rsqrtf(fmaxf((float)__ldg(deg + v), 1.0f));
        float4 f4 = h4_to_f4(__ldg(fh + (size_t)v * 8 + c));
        float4 t;
        t.x = (-r * acc.x * dv + (r - 1.0f) * f4.x) * dv;
        t.y = (-r * acc.y * dv + (r - 1.0f) * f4.y) * dv;
        t.z = (-r * acc.z * dv + (r - 1.0f) * f4.z) * dv;
        t.w = (-r * acc.w * dv + (r - 1.0f) * f4.w) * dv;
        Tout[(size_t)v * 8 + c] = f4_to_h4(t);
    }
}

// chebBL layer1: X1 reconstructed from T1h row; f = emb fp32.
// h1h = half(leaky(GEMV)); T0h = half(h * dv)
__global__ void k_chebBL1(const int* __restrict__ rs, const int* __restrict__ csr_src,
                          const uint2* __restrict__ Tin, const float4* __restrict__ f,
                          const int* __restrict__ deg, const float* __restrict__ lam,
                          const __half2* __restrict__ Wc, const float* __restrict__ b,
                          __half* __restrict__ h1h, __half* __restrict__ Tout, int n) {
    __shared__ float sX[8][96];
    int v = blockIdx.x * 8 + threadIdx.y;
    if (v >= n) return;
    int lane = threadIdx.x;
    int g = lane >> 3, c = lane & 7;
    int beg = rs[v], end = rs[v + 1];
    float4 acc = row_sum4h(beg, end, csr_src, Tin, g, c);
    float di = fmaxf((float)__ldg(deg + v), 1.0f);
    float dv = rsqrtf(di);
    if (g == 0) {
        float r = 2.0f / lam[0];
        float sdeg = di * dv;  // sqrt(di)
        float4 t1 = h4_to_f4(__ldg((const uint2*)Tin + (size_t)v * 8 + c));
        float4 x1;
        x1.x = t1.x * sdeg; x1.y = t1.y * sdeg;
        x1.z = t1.z * sdeg; x1.w = t1.w * sdeg;
        float4 f4 = __ldg(f + (size_t)v * 8 + c);
        float4 x2;
        x2.x = -2.0f * r * acc.x * dv + 2.0f * (r - 1.0f) * x1.x - f4.x;
        x2.y = -2.0f * r * acc.y * dv + 2.0f * (r - 1.0f) * x1.y - f4.y;
        x2.z = -2.0f * r * acc.z * dv + 2.0f * (r - 1.0f) * x1.z - f4.z;
        x2.w = -2.0f * r * acc.w * dv + 2.0f * (r - 1.0f) * x1.w - f4.w;
        float* sx = sX[threadIdx.y];
        sx[c * 4 + 0] = f4.x;  sx[c * 4 + 1] = f4.y;
        sx[c * 4 + 2] = f4.z;  sx[c * 4 + 3] = f4.w;
        sx[32 + c * 4 + 0] = x1.x;  sx[32 + c * 4 + 1] = x1.y;
        sx[32 + c * 4 + 2] = x1.z;  sx[32 + c * 4 + 3] = x1.w;
        sx[64 + c * 4 + 0] = x2.x;  sx[64 + c * 4 + 1] = x2.y;
        sx[64 + c * 4 + 2] = x2.z;  sx[64 + c * 4 + 3] = x2.w;
    }
    __syncwarp();
    const float2* sx2 = (const float2*)sX[threadIdx.y];
    float s = __ldg(b + lane);
#pragma unroll
    for (int j2 = 0; j2 < 48; j2++) {
        float2 x = sx2[j2];
        float2 w = __half22float2(__ldg(Wc + j2 * 32 + lane));
        s += x.x * w.x + x.y * w.y;
    }
    s = leaky(s, 0.01f);
    h1h[(size_t)v * ND + lane] = __float2half(s);
    Tout[(size_t)v * ND + lane] = __float2half(s * dv);
}

// chebBL layer2: f = h1 fp16; epilogue computes fs/fd directly (h stays on-chip)
__global__ void k_chebBL2(const int* __restrict__ rs, const int* __restrict__ csr_src,
                          const uint2* __restrict__ Tin, const uint2* __restrict__ fh,
                          const int* __restrict__ deg, const float* __restrict__ lam,
                          const __half2* __restrict__ Wc, const float* __restrict__ b,
                          const float* __restrict__ bsrc, const float* __restrict__ bdst,
                          __half* __restrict__ fsh, __half* __restrict__ fdh, int n) {
    __shared__ float sX[8][96];
    __shared__ float sH[8][32];
    int v = blockIdx.x * 8 + threadIdx.y;
    if (v >= n) return;
    int lane = threadIdx.x;
    int g = lane >> 3, c = lane & 7;
    int beg = rs[v], end = rs[v + 1];
    float4 acc = row_sum4h(beg, end, csr_src, Tin, g, c);
    float di = fmaxf((float)__ldg(deg + v), 1.0f);
    float dv = rsqrtf(di);
    if (g == 0) {
        float r = 2.0f / lam[0];
        float sdeg = di * dv;
        float4 t1 = h4_to_f4(__ldg((const uint2*)Tin + (size_t)v * 8 + c));
        float4 x1;
        x1.x = t1.x * sdeg; x1.y = t1.y * sdeg;
        x1.z = t1.z * sdeg; x1.w = t1.w * sdeg;
        float4 f4 = h4_to_f4(__ldg(fh + (size_t)v * 8 + c));
        float4 x2;
        x2.x = -2.0f * r * acc.x * dv + 2.0f * (r - 1.0f) * x1.x - f4.x;
        x2.y = -2.0f * r * acc.y * dv + 2.0f * (r - 1.0f) * x1.y - f4.y;
        x2.z = -2.0f * r * acc.z * dv + 2.0f * (r - 1.0f) * x1.z - f4.z;
        x2.w = -2.0f * r * acc.w * dv + 2.0f * (r - 1.0f) * x1.w - f4.w;
        float* sx = sX[threadIdx.y];
        sx[c * 4 + 0] = f4.x;  sx[c * 4 + 1] = f4.y;
        sx[c * 4 + 2] = f4.z;  sx[c * 4 + 3] = f4.w;
        sx[32 + c * 4 + 0] = x1.x;  sx[32 + c * 4 + 1] = x1.y;
        sx[32 + c * 4 + 2] = x1.z;  sx[32 + c * 4 + 3] = x1.w;
        sx[64 + c * 4 + 0] = x2.x;  sx[64 + c * 4 + 1] = x2.y;
        sx[64 + c * 4 + 2] = x2.z;  sx[64 + c * 4 + 3] = x2.w;
    }
    __syncwarp();
    const float2* sx2 = (const float2*)sX[threadIdx.y];
    float s = __ldg(b + lane);
#pragma unroll
    for (int j2 = 0; j2 < 48; j2++) {
        float2 x = sx2[j2];
        float2 w = __half22float2(__ldg(Wc + j2 * 32 + lane));
        s += x.x * w.x + x.y * w.y;
    }
    s = leaky(s, 0.01f);
    sH[threadIdx.y][lane] = s;
    __syncwarp();
    const float2* sh2 = (const float2*)sH[threadIdx.y];
    float a = __ldg(bsrc + lane), d = __ldg(bdst + lane);
    const __half2* Ws2 = Wc + 48 * 32;
    const __half2* Wd2 = Wc + 64 * 32;
#pragma unroll
    for (int j2 = 0; j2 < 16; j2++) {
        float2 x = sh2[j2];
        float2 ws = __half22float2(__ldg(Ws2 + j2 * 32 + lane));
        float2 wd = __half22float2(__ldg(Wd2 + j2 * 32 + lane));
        a += x.x * ws.x + x.y * ws.y;
        d += x.x * wd.x + x.y * wd.y;
    }
    fsh[(size_t)v * ND + lane] = __float2half(a);
    fdh[(size_t)v * ND + lane] = __float2half(d);
}

// ---------------------------------------------------------------------------
// fused GATv2: one CSR pass, plain softmax (shift-invariant; logits O(10)),
// 4 edges x 8 lanes per warp, fs/fd rows fp16. Re-zeros deg for next run.
// ---------------------------------------------------------------------------
__device__ __forceinline__ float edge_logit(float4 f0, float4 fd4, float4 w) {
    float t = leaky(f0.x + fd4.x, 0.2f) * w.x + leaky(f0.y + fd4.y, 0.2f) * w.y +
              leaky(f0.z + fd4.z, 0.2f) * w.z + leaky(f0.w + fd4.w, 0.2f) * w.w;
    t += __shfl_xor_sync(0xffffffffu, t, 1);
    t += __shfl_xor_sync(0xffffffffu, t, 2);
    t += __shfl_xor_sync(0xffffffffu, t, 4);
    return t;
}

__global__ void k_gat(const int* __restrict__ rs, const int* __restrict__ csr_src,
                      const uint2* __restrict__ fsh, const uint2* __restrict__ fdh,
                      const float4* __restrict__ attn, float4* __restrict__ out,
                      int* __restrict__ deg, int n) {
    int v = blockIdx.x * 8 + threadIdx.y;
    if (v >= n) return;
    int lane = threadIdx.x;
    int g = lane >> 3, c = lane & 7;
    int beg = rs[v], end = rs[v + 1];
    float4 fd4 = h4_to_f4(__ldg(fdh + (size_t)v * 8 + c));
    float4 w = __ldg(attn + c);
    float den = 0.0f;
    float4 acc = make_float4(0.f, 0.f, 0.f, 0.f);
    int base = beg;
    for (; base + 8 <= end; base += 8) {
        int s0 = __ldg(csr_src + base + g);
        int s1 = __ldg(csr_src + base + 4 + g);
        float4 f0 = h4_to_f4(__ldg(fsh + (size_t)s0 * 8 + c));
        float4 f1 = h4_to_f4(__ldg(fsh + (size_t)s1 * 8 + c));
        float t0 = edge_logit(f0, fd4, w);
        float t1 = edge_logit(f1, fd4, w);
        float e0 = __expf(t0);
        float e1 = __expf(t1);
        den += e0 + e1;
        acc.x += f0.x * e0 + f1.x * e1;
        acc.y += f0.y * e0 + f1.y * e1;
        acc.z += f0.z * e0 + f1.z * e1;
        acc.w += f0.w * e0 + f1.w * e1;
    }
    for (; base < end; base += 4) {
        int p = base + g;
        bool valid = p < end;
        int s0 = valid ? __ldg(csr_src + p) : 0;
        float4 f0 = h4_to_f4(__ldg(fsh + (size_t)s0 * 8 + c));
        float t0 = edge_logit(f0, fd4, w);  // all lanes participate in shfl
        if (valid) {
            float e0 = __expf(t0);
            den += e0;
            acc.x += f0.x * e0;
            acc.y += f0.y * e0;
            acc.z += f0.z * e0;
            acc.w += f0.w * e0;
        }
    }
#pragma unroll
    for (int o = 8; o <= 16; o <<= 1) {
        den   += __shfl_xor_sync(0xffffffffu, den,   o);
        acc.x += __shfl_xor_sync(0xffffffffu, acc.x, o);
        acc.y += __shfl_xor_sync(0xffffffffu, acc.y, o);
        acc.z += __shfl_xor_sync(0xffffffffu, acc.z, o);
        acc.w += __shfl_xor_sync(0xffffffffu, acc.w, o);
    }
    if (g == 0) {
        float inv = (den > 0.0f) ? 1.0f / den : 0.0f;
        float4 o;
        o.x = leaky(acc.x * inv, 0.01f);
        o.y = leaky(acc.y * inv, 0.01f);
        o.z = leaky(acc.z * inv, 0.01f);
        o.w = leaky(acc.w * inv, 0.01f);
        out[(size_t)v * 8 + c] = o;
        if (c == 0) deg[v] = 0;  // ready for next run / replay
    }
}

// ---------------------------------------------------------------------------
// launch
// ---------------------------------------------------------------------------
extern "C" void kernel_launch(void* const* d_in, const int* in_sizes, int n_in,
                              void* d_out, int out_size) {
    const int*   src  = (const int*)d_in[0];
    const int*   dst  = (const int*)d_in[1];
    const float* emb  = (const float*)d_in[2];
    const float* lam  = (const float*)d_in[3];
    const float* chW  = (const float*)d_in[4];
    const float* chb  = (const float*)d_in[5];
    const float* Ws   = (const float*)d_in[6];
    const float* bs   = (const float*)d_in[7];
    const float* Wd   = (const float*)d_in[8];
    const float* bd   = (const float*)d_in[9];
    const float* attn = (const float*)d_in[10];

    const int E = in_sizes[0];
    const int n = in_sizes[2] / ND;

    float* base = nullptr;
    cudaGetSymbolAddress((void**)&base, g_buf);

    __half* h1h     = (__half*)base;
    __half* T0h     = (__half*)(base + SLOT / 2);
    __half* T1h     = (__half*)(base + SLOT);
    __half* fsh     = (__half*)(base + 3 * SLOT / 2);
    __half* fdh     = (__half*)(base + 2 * SLOT);
    int*    csr_src = (int*)(base + 5 * SLOT / 2);
    float*  tail    = base + 5 * SLOT / 2 + MAXE;
    int*    deg     = (int*)tail;
    int*    rs      = (int*)(tail + MAXN);          // N+1
    int*    cursor  = (int*)(tail + 2 * MAXN + 64);
    int*    blk     = (int*)(tail + 3 * MAXN + 64);
    __half2* wc     = (__half2*)(tail + 3 * MAXN + 256);  // 2560 half2

    const int nt = 256;
    auto g = [&](long x) { return (int)((x + nt - 1) / nt); };
    const int gV4   = g((long)n * 8);
    const int gEdge = g((long)E);
    const int gNW   = (n + 7) / 8;
    dim3 bNW(32, 8);
    const int nb = (n + 1023) / 1024;

    // --- CSR build + fused weight conversion ---
    k_deg<<<gEdge + 10, nt>>>(dst, deg, E, gEdge, chW, Ws, Wd, wc);
    k_scan1<<<nb, 1024>>>(deg, rs, blk, n);
    k_scan2<<<1, 128>>>(blk, nb);
    k_scan3p<<<gV4, nt>>>(rs, cursor, blk, deg, (const float4*)emb, (uint2*)T0h, n, E);
    k_fill<<<gEdge, nt>>>(src, dst, cursor, csr_src, E);

    // --- ChebConv 1 (input = embedding) ---
    k_chebA1<<<gNW, bNW>>>(rs, csr_src, (const uint2*)T0h, (const float4*)emb,
                           deg, lam, (uint2*)T1h, n);
    k_chebBL1<<<gNW, bNW>>>(rs, csr_src, (const uint2*)T1h, (const float4*)emb,
                            deg, lam, wc, chb, h1h, T0h, n);

    // --- ChebConv 2 (input = h1 fp16; T0h = h1*dinv) + fused GAT projections ---
    k_chebA2<<<gNW, bNW>>>(rs, csr_src, (const uint2*)T0h, (const uint2*)h1h,
                           deg, lam, (uint2*)T1h, n);
    k_chebBL2<<<gNW, bNW>>>(rs, csr_src, (const uint2*)T1h, (const uint2*)h1h,
                            deg, lam, wc, chb, bs, bd, fsh, fdh, n);

    // --- GATv2 (fused single pass, fp16 fs/fd, plain softmax) ---
    k_gat<<<gNW, bNW>>>(rs, csr_src, (const uint2*)fsh, (const uint2*)fdh,
                        (const float4*)attn, (float4*)d_out, deg, n);
}